// round 10
// baseline (speedup 1.0000x reference)
#include <cuda_runtime.h>
#include <cstdint>

// Problem constants
#define S 2048
#define D 1024
#define H 16
#define DI 64
#define DV 64
#define DFF 4096
#define SA_ELEMS ((size_t)H * S * S)   // 67108864

// -------------------- scratch (device globals) -----------------------------
__device__ float g_WqkvT[(size_t)(3 * D) * D];   // packed transposed, tf32-rounded
__device__ float g_QKV[(size_t)S * 3 * D];       // [S, 3072] full fp32
__device__ float g_Z[(size_t)S * D];             // tf32-rounded (av epilogue)
__device__ float g_ATT[(size_t)S * D];           // full fp32 (residual)
__device__ float g_ATTc[(size_t)S * D];          // tf32-rounded copy
__device__ float g_H1[(size_t)S * DFF];          // tf32-rounded (FF1 epilogue)
__device__ float g_Xc[(size_t)S * D];            // tf32-rounded input
__device__ float g_WOc[(size_t)D * D];           // tf32-rounded WO_w
__device__ float g_FF1c[(size_t)DFF * D];        // tf32-rounded FF1_w
__device__ float g_FF2c[(size_t)D * DFF];        // tf32-rounded FF2_w

// -------------------- helpers ---------------------------------------------
__device__ __forceinline__ unsigned f2tf32(float x) {
    unsigned u;
    asm("cvt.rna.tf32.f32 %0, %1;" : "=r"(u) : "f"(x));
    return u;
}
__device__ __forceinline__ float f2tf32f(float x) { return __uint_as_float(f2tf32(x)); }

__device__ __forceinline__ float4 cvt4(float4 v) {
    float4 t;
    t.x = f2tf32f(v.x); t.y = f2tf32f(v.y);
    t.z = f2tf32f(v.z); t.w = f2tf32f(v.w);
    return t;
}

__device__ __forceinline__ void ldsm_x4(unsigned& r0, unsigned& r1, unsigned& r2, unsigned& r3,
                                        const float* p) {
    unsigned addr = (unsigned)__cvta_generic_to_shared(p);
    asm volatile("ldmatrix.sync.aligned.m8n8.x4.shared.b16 {%0,%1,%2,%3}, [%4];"
                 : "=r"(r0), "=r"(r1), "=r"(r2), "=r"(r3) : "r"(addr));
}

__device__ __forceinline__ void mma_tf32(float* c, const unsigned* a, const unsigned* b) {
    asm volatile(
        "mma.sync.aligned.m16n8k8.row.col.f32.tf32.tf32.f32 "
        "{%0,%1,%2,%3}, {%4,%5,%6,%7}, {%8,%9}, {%0,%1,%2,%3};"
        : "+f"(c[0]), "+f"(c[1]), "+f"(c[2]), "+f"(c[3])
        : "r"(a[0]), "r"(a[1]), "r"(a[2]), "r"(a[3]), "r"(b[0]), "r"(b[1]));
}

__device__ __forceinline__ void cp_async16(float* smem_dst, const float* gsrc) {
    unsigned dst = (unsigned)__cvta_generic_to_shared(smem_dst);
    asm volatile("cp.async.cg.shared.global [%0], [%1], 16;" :: "r"(dst), "l"(gsrc));
}
__device__ __forceinline__ void cp_commit() {
    asm volatile("cp.async.commit_group;");
}
template <int N>
__device__ __forceinline__ void cp_wait() {
    asm volatile("cp.async.wait_group %0;" :: "n"(N));
}

// -------------------- elementwise tf32 round (pre-convert) -----------------
__global__ void cvt_kernel(const float* __restrict__ in, float* __restrict__ out, int n4) {
    int i = blockIdx.x * 256 + threadIdx.x;
    if (i >= n4) return;
    float4 v = *(const float4*)(in + (size_t)i * 4);
    *(float4*)(out + (size_t)i * 4) = cvt4(v);
}

// -------------------- pack WQ/WK/WV transposed + round: [3072, 1024] -------
__global__ void pack_w_kernel(const float* __restrict__ WQ,
                              const float* __restrict__ WK,
                              const float* __restrict__ WV) {
    int idx = blockIdx.x * 256 + threadIdx.x;   // n*1024 + d
    if (idx >= 3 * D * D) return;
    int d = idx & 1023;
    int n = idx >> 10;
    int sect = n >> 10;
    int nn = n & 1023;
    int h = nn >> 6, e = nn & 63;
    const float* W = (sect == 0) ? WQ : (sect == 1) ? WK : WV;
    g_WqkvT[idx] = f2tf32f(W[((size_t)h * D + d) * 64 + e]);
}

// ---- tf32 GEMM, cp.async 4-stage, 128 x BN tiles: C = A[MxK]*B[NxK]^T -----
// Operands must be tf32-pre-rounded in gmem.
// EPI: 0 = write C
//      1 = C = acc + bias[n] + res[m,n]
//      2 = C = tf32(relu(acc + bias[n]))
//      3 = C = acc + bias[n] + res[m,n], C2 = tf32(C)
template <int BN, int EPI>
__global__ __launch_bounds__(256, 1)
void tf32gemm_ca(const float* __restrict__ A, const float* __restrict__ B,
                 const float* __restrict__ bias, const float* __restrict__ res,
                 float* __restrict__ C, float* __restrict__ C2,
                 int M, int N, int K) {
    const int BM = 128, BK = 16, LDS_ = 20, STG = 4;
    const int NT = BN / 16;                 // n8-tile count per warpN
    extern __shared__ float smemf[];
    float* As = smemf;                       // STG stages of BM*LDS_
    float* Bs = smemf + STG * BM * LDS_;     // STG stages of BN*LDS_

    int tid = threadIdx.x;
    int lane = tid & 31, warp = tid >> 5;
    int warpM = warp >> 1, warpN = warp & 1;     // 4 x 2 warp grid
    int bm = blockIdx.y * BM, bn = blockIdx.x * BN;

    float acc[2][NT][4];
#pragma unroll
    for (int i = 0; i < 2; i++)
#pragma unroll
        for (int j = 0; j < NT; j++)
#pragma unroll
            for (int r = 0; r < 4; r++) acc[i][j][r] = 0.f;

    int a_row = warpM * 32 + (lane & 15);
    int a_col = (lane >> 4) * 4;
    int b_row = warpN * (BN / 2) + (lane & 7) + ((lane >> 4) << 3);
    int b_col = ((lane >> 3) & 1) * 4;

    // load mapping: id -> row id>>2, col (id&3)*4
    int ld_r = tid >> 2, ld_c4 = (tid & 3) * 4;
    const float* Ap = A + (size_t)(bm + ld_r) * K + ld_c4;
    const float* Bp = B + (size_t)(bn + ld_r) * K + ld_c4;
    size_t rowoffA = (size_t)64 * K;          // +64 rows

    int nk = K / BK;

    // prologue: issue stages 0..STG-2
#pragma unroll
    for (int s = 0; s < STG - 1; s++) {
        float* Asb = As + s * BM * LDS_;
        float* Bsb = Bs + s * BN * LDS_;
        const float* Ak = Ap + (size_t)s * BK;
        const float* Bk = Bp + (size_t)s * BK;
#pragma unroll
        for (int i = 0; i < BM / 64; i++)
            cp_async16(Asb + (ld_r + i * 64) * LDS_ + ld_c4, Ak + i * rowoffA);
#pragma unroll
        for (int i = 0; i < BN / 64; i++)
            cp_async16(Bsb + (ld_r + i * 64) * LDS_ + ld_c4, Bk + i * rowoffA);
        cp_commit();
    }

    for (int kt = 0; kt < nk; kt++) {
        cp_wait<STG - 2>();
        __syncthreads();

        if (kt + STG - 1 < nk) {
            int s = (kt + STG - 1) % STG;
            float* Asb = As + s * BM * LDS_;
            float* Bsb = Bs + s * BN * LDS_;
            const float* Ak = Ap + (size_t)(kt + STG - 1) * BK;
            const float* Bk = Bp + (size_t)(kt + STG - 1) * BK;
#pragma unroll
            for (int i = 0; i < BM / 64; i++)
                cp_async16(Asb + (ld_r + i * 64) * LDS_ + ld_c4, Ak + i * rowoffA);
#pragma unroll
            for (int i = 0; i < BN / 64; i++)
                cp_async16(Bsb + (ld_r + i * 64) * LDS_ + ld_c4, Bk + i * rowoffA);
            cp_commit();
        }

        const float* Asb = As + (kt % STG) * BM * LDS_;
        const float* Bsb = Bs + (kt % STG) * BN * LDS_;
#pragma unroll
        for (int ks = 0; ks < 2; ks++) {
            unsigned af[2][4];
            unsigned bf[NT][2];
#pragma unroll
            for (int mt = 0; mt < 2; mt++) {
                ldsm_x4(af[mt][0], af[mt][1], af[mt][2], af[mt][3],
                        &Asb[(a_row + mt * 16) * LDS_ + ks * 8 + a_col]);
            }
#pragma unroll
            for (int np = 0; np < NT / 2; np++) {
                ldsm_x4(bf[2 * np][0], bf[2 * np][1], bf[2 * np + 1][0], bf[2 * np + 1][1],
                        &Bsb[(b_row + np * 16) * LDS_ + ks * 8 + b_col]);
            }
#pragma unroll
            for (int mt = 0; mt < 2; mt++)
#pragma unroll
                for (int nt = 0; nt < NT; nt++)
                    mma_tf32(acc[mt][nt], af[mt], bf[nt]);
        }
    }

    int g = lane >> 2, c2 = (lane & 3) * 2;
#pragma unroll
    for (int mt = 0; mt < 2; mt++) {
#pragma unroll
        for (int half = 0; half < 2; half++) {
            int m = bm + warpM * 32 + mt * 16 + g + half * 8;
#pragma unroll
            for (int nt = 0; nt < NT; nt++) {
                int n = bn + warpN * (BN / 2) + nt * 8 + c2;
                float v0 = acc[mt][nt][half * 2 + 0];
                float v1 = acc[mt][nt][half * 2 + 1];
                if (EPI >= 1) { v0 += bias[n]; v1 += bias[n + 1]; }
                if (EPI == 1 || EPI == 3) {
                    float2 rr = *(const float2*)(res + (size_t)m * N + n);
                    v0 += rr.x; v1 += rr.y;
                }
                if (EPI == 2) {
                    v0 = f2tf32f(fmaxf(v0, 0.f));
                    v1 = f2tf32f(fmaxf(v1, 0.f));
                }
                float2 o; o.x = v0; o.y = v1;
                *(float2*)(C + (size_t)m * N + n) = o;
                if (EPI == 3) {
                    float2 oc; oc.x = f2tf32f(v0); oc.y = f2tf32f(v1);
                    *(float2*)(C2 + (size_t)m * N + n) = oc;
                }
            }
        }
    }
}

// -------------------- scores (tensor cores, 3xTF32 for fp32 accuracy) ------
__global__ __launch_bounds__(256)
void scores_tc_kernel(const float* __restrict__ QKV, float* __restrict__ SA) {
    const int LDS_ = 20;
    int jt = blockIdx.x, it = blockIdx.y, h = blockIdx.z;
    int bm = it * 128, bn = jt * 128;
    float* out = SA + ((size_t)h * S + bm) * S + bn;
    int tid = threadIdx.x;

    if (jt > it) {   // strictly above diagonal at 128-granularity: zeros
#pragma unroll
        for (int r = 0; r < 16; r++) {
            int id = tid + r * 256;
            int row = id >> 5, c4 = (id & 31) * 4;
            *(float4*)(out + (size_t)row * S + c4) = make_float4(0.f, 0.f, 0.f, 0.f);
        }
        return;
    }

    __shared__ float Qh[128 * LDS_], Ql[128 * LDS_];
    __shared__ float Kh[128 * LDS_], Kl[128 * LDS_];

    int lane = tid & 31, warp = tid >> 5;
    int warpM = warp >> 1, warpN = warp & 1;

    float acc[2][8][4];
#pragma unroll
    for (int i = 0; i < 2; i++)
#pragma unroll
        for (int j = 0; j < 8; j++)
#pragma unroll
            for (int r = 0; r < 4; r++) acc[i][j][r] = 0.f;

    int a_row = warpM * 32 + (lane & 15);
    int a_col = (lane >> 4) * 4;
    int b_row = warpN * 64 + (lane & 7) + ((lane >> 4) << 3);
    int b_col = ((lane >> 3) & 1) * 4;

    const float* Qb = QKV + (size_t)bm * (3 * D) + h * 64;
    const float* Kb = QKV + (size_t)bn * (3 * D) + D + h * 64;

    for (int kc = 0; kc < 4; kc++) {
#pragma unroll
        for (int i = 0; i < 2; i++) {
            int id = tid + i * 256;
            int row = id >> 2, c4 = (id & 3) * 4;
            float4 q = *(const float4*)(Qb + (size_t)row * (3 * D) + kc * 16 + c4);
            float4 k = *(const float4*)(Kb + (size_t)row * (3 * D) + kc * 16 + c4);
            float4 qh = cvt4(q), kh = cvt4(k);
            float4 ql, kl;
            ql.x = f2tf32f(q.x - qh.x); ql.y = f2tf32f(q.y - qh.y);
            ql.z = f2tf32f(q.z - qh.z); ql.w = f2tf32f(q.w - qh.w);
            kl.x = f2tf32f(k.x - kh.x); kl.y = f2tf32f(k.y - kh.y);
            kl.z = f2tf32f(k.z - kh.z); kl.w = f2tf32f(k.w - kh.w);
            *(float4*)&Qh[row * LDS_ + c4] = qh;
            *(float4*)&Ql[row * LDS_ + c4] = ql;
            *(float4*)&Kh[row * LDS_ + c4] = kh;
            *(float4*)&Kl[row * LDS_ + c4] = kl;
        }
        __syncthreads();

#pragma unroll
        for (int ks = 0; ks < 2; ks++) {
            unsigned afh[2][4], afl[2][4];
            unsigned bfh[8][2], bfl[8][2];
#pragma unroll
            for (int mt = 0; mt < 2; mt++) {
                ldsm_x4(afh[mt][0], afh[mt][1], afh[mt][2], afh[mt][3],
                        &Qh[(a_row + mt * 16) * LDS_ + ks * 8 + a_col]);
                ldsm_x4(afl[mt][0], afl[mt][1], afl[mt][2], afl[mt][3],
                        &Ql[(a_row + mt * 16) * LDS_ + ks * 8 + a_col]);
            }
#pragma unroll
            for (int np = 0; np < 4; np++) {
                ldsm_x4(bfh[2 * np][0], bfh[2 * np][1], bfh[2 * np + 1][0], bfh[2 * np + 1][1],
                        &Kh[(b_row + np * 16) * LDS_ + ks * 8 + b_col]);
                ldsm_x4(bfl[2 * np][0], bfl[2 * np][1], bfl[2 * np + 1][0], bfl[2 * np + 1][1],
                        &Kl[(b_row + np * 16) * LDS_ + ks * 8 + b_col]);
            }
#pragma unroll
            for (int mt = 0; mt < 2; mt++)
#pragma unroll
                for (int nt = 0; nt < 8; nt++) {
                    mma_tf32(acc[mt][nt], afh[mt], bfh[nt]);
                    mma_tf32(acc[mt][nt], afh[mt], bfl[nt]);
                    mma_tf32(acc[mt][nt], afl[mt], bfh[nt]);
                }
        }
        __syncthreads();
    }

    float slope = exp2f(-0.5f * (float)(h + 1));
    int g = lane >> 2, c2 = (lane & 3) * 2;
#pragma unroll
    for (int mt = 0; mt < 2; mt++) {
#pragma unroll
        for (int half = 0; half < 2; half++) {
            int li = warpM * 32 + mt * 16 + g + half * 8;
            int gi = bm + li;
#pragma unroll
            for (int nt = 0; nt < 8; nt++) {
                int lj = warpN * 64 + nt * 8 + c2;
                int gj = bn + lj;
                float v0 = acc[mt][nt][half * 2 + 0];
                float v1 = acc[mt][nt][half * 2 + 1];
                v0 = (gj <= gi) ? (v0 * 0.125f - (float)(gi - gj) * slope) : 0.f;
                v1 = (gj + 1 <= gi) ? (v1 * 0.125f - (float)(gi - gj - 1) * slope) : 0.f;
                float2 o; o.x = v0; o.y = v1;
                *(float2*)(out + (size_t)li * S + lj) = o;
            }
        }
    }
}

// -------------------- in-place causal row softmax (vectorized) -------------
__global__ __launch_bounds__(256)
void softmax_kernel(float* __restrict__ SA) {
    int row = blockIdx.x;           // h*S + i
    int i = row & (S - 1);
    float* p = SA + (size_t)row * S;
    int t = threadIdx.x;
    __shared__ float red[8];

    float v[8];
    float mx = -1e30f;
#pragma unroll
    for (int r = 0; r < 2; r++) {
        int j = r * 1024 + t * 4;
        float4 x4 = *(const float4*)(p + j);
        float xv[4] = {x4.x, x4.y, x4.z, x4.w};
#pragma unroll
        for (int q = 0; q < 4; q++) {
            float x = (j + q <= i) ? xv[q] : -1e30f;
            v[r * 4 + q] = x;
            mx = fmaxf(mx, x);
        }
    }
#pragma unroll
    for (int o = 16; o > 0; o >>= 1) mx = fmaxf(mx, __shfl_xor_sync(0xffffffffu, mx, o));
    if ((t & 31) == 0) red[t >> 5] = mx;
    __syncthreads();
    float bm = red[0];
#pragma unroll
    for (int w = 1; w < 8; w++) bm = fmaxf(bm, red[w]);
    __syncthreads();

    float sum = 0.f;
#pragma unroll
    for (int r = 0; r < 8; r++) {
        float e = __expf(v[r] - bm);
        v[r] = e;
        sum += e;
    }
#pragma unroll
    for (int o = 16; o > 0; o >>= 1) sum += __shfl_xor_sync(0xffffffffu, sum, o);
    if ((t & 31) == 0) red[t >> 5] = sum;
    __syncthreads();
    float bs = 0.f;
#pragma unroll
    for (int w = 0; w < 8; w++) bs += red[w];
    float inv = 1.f / bs;
#pragma unroll
    for (int r = 0; r < 2; r++) {
        int j = r * 1024 + t * 4;
        if (j + 3 <= i) {
            float4 o;
            o.x = v[r * 4 + 0] * inv; o.y = v[r * 4 + 1] * inv;
            o.z = v[r * 4 + 2] * inv; o.w = v[r * 4 + 3] * inv;
            *(float4*)(p + j) = o;
        } else {
#pragma unroll
            for (int q = 0; q < 4; q++)
                if (j + q <= i) p[j + q] = v[r * 4 + q] * inv;
        }
    }
}

// -------------------- z = SA @ V (tensor cores, tf32; Z written rounded) ---
__global__ __launch_bounds__(256)
void av_tc_kernel(const float* __restrict__ SA, const float* __restrict__ QKV,
                  float* __restrict__ Z) {
    const int LDS_ = 20;
    int bi = blockIdx.x, h = blockIdx.y;
    int bm = bi * 128;
    int tid = threadIdx.x;
    int lane = tid & 31, warp = tid >> 5;

    __shared__ float SAs[128 * LDS_];
    __shared__ float Vs[64 * LDS_];

    float acc[8][4];
#pragma unroll
    for (int j = 0; j < 8; j++)
#pragma unroll
        for (int r = 0; r < 4; r++) acc[j][r] = 0.f;

    int a_row = warp * 16 + (lane & 15);
    int a_col = (lane >> 4) * 4;
    int b_row = (lane & 7) + ((lane >> 4) << 3);
    int b_col = ((lane >> 3) & 1) * 4;

    const float* SAb = SA + ((size_t)h * S + bm) * S;
    const float* Vb = QKV + 2 * D + (size_t)h * 64;

    int nchunks = (bm + 128) / 16;
    for (int kc = 0; kc < nchunks; kc++) {
        int k0 = kc * 16;
#pragma unroll
        for (int i = 0; i < 2; i++) {
            int id = tid + i * 256;
            int row = id >> 2, c4 = (id & 3) * 4;
            float4 a = *(const float4*)(SAb + (size_t)row * S + k0 + c4);
            *(float4*)&SAs[row * LDS_ + c4] = cvt4(a);
        }
        {
            int jloc = tid >> 6, v = tid & 63;
#pragma unroll
            for (int i = 0; i < 4; i++) {
                int jj = jloc + i * 4;
                float x = Vb[(size_t)(k0 + jj) * (3 * D) + v];
                Vs[v * LDS_ + jj] = f2tf32f(x);
            }
        }
        __syncthreads();

#pragma unroll
        for (int ks = 0; ks < 2; ks++) {
            unsigned af[4];
            unsigned bf[8][2];
            ldsm_x4(af[0], af[1], af[2], af[3],
                    &SAs[a_row * LDS_ + ks * 8 + a_col]);
#pragma unroll
            for (int np = 0; np < 4; np++) {
                ldsm_x4(bf[2 * np][0], bf[2 * np][1], bf[2 * np + 1][0], bf[2 * np + 1][1],
                        &Vs[(b_row + np * 16) * LDS_ + ks * 8 + b_col]);
            }
#pragma unroll
            for (int nt = 0; nt < 8; nt++)
                mma_tf32(acc[nt], af, bf[nt]);
        }
        __syncthreads();
    }

    int g = lane >> 2, c2 = (lane & 3) * 2;
#pragma unroll
    for (int half = 0; half < 2; half++) {
        int m = bm + warp * 16 + g + half * 8;
#pragma unroll
        for (int nt = 0; nt < 8; nt++) {
            int n = h * 64 + nt * 8 + c2;
            float2 o;
            o.x = f2tf32f(acc[nt][half * 2 + 0]);   // Z feeds only the WO GEMM
            o.y = f2tf32f(acc[nt][half * 2 + 1]);
            *(float2*)(Z + (size_t)m * D + n) = o;
        }
    }
}

// --------------------------- launch ---------------------------------------
extern "C" void kernel_launch(void* const* d_in, const int* in_sizes, int n_in,
                              void* d_out, int out_size) {
    const float* X    = (const float*)d_in[0];
    const float* WQ   = (const float*)d_in[1];
    const float* WK   = (const float*)d_in[2];
    const float* WV   = (const float*)d_in[3];
    const float* WOw  = (const float*)d_in[4];
    const float* WOb  = (const float*)d_in[5];
    const float* FF1w = (const float*)d_in[6];
    const float* FF1b = (const float*)d_in[7];
    const float* FF2w = (const float*)d_in[8];
    const float* FF2b = (const float*)d_in[9];

    float* SA  = (float*)d_out;
    float* OUT = (float*)d_out + SA_ELEMS;

    float *WqkvT, *QKV, *Z, *ATT, *ATTc, *H1, *Xc, *WOc, *FF1c, *FF2c;
    cudaGetSymbolAddress((void**)&WqkvT, g_WqkvT);
    cudaGetSymbolAddress((void**)&QKV, g_QKV);
    cudaGetSymbolAddress((void**)&Z, g_Z);
    cudaGetSymbolAddress((void**)&ATT, g_ATT);
    cudaGetSymbolAddress((void**)&ATTc, g_ATTc);
    cudaGetSymbolAddress((void**)&H1, g_H1);
    cudaGetSymbolAddress((void**)&Xc, g_Xc);
    cudaGetSymbolAddress((void**)&WOc, g_WOc);
    cudaGetSymbolAddress((void**)&FF1c, g_FF1c);
    cudaGetSymbolAddress((void**)&FF2c, g_FF2c);

    // dynamic smem: 4 stages x (128 + BN) rows x 20 floats
    const int SMEM256 = 4 * (128 + 256) * 20 * 4;   // 122880
    const int SMEM128 = 4 * (128 + 128) * 20 * 4;   // 81920
    cudaFuncSetAttribute(tf32gemm_ca<256, 0>, cudaFuncAttributeMaxDynamicSharedMemorySize, SMEM256);
    cudaFuncSetAttribute(tf32gemm_ca<256, 2>, cudaFuncAttributeMaxDynamicSharedMemorySize, SMEM256);
    cudaFuncSetAttribute(tf32gemm_ca<128, 3>, cudaFuncAttributeMaxDynamicSharedMemorySize, SMEM128);
    cudaFuncSetAttribute(tf32gemm_ca<128, 1>, cudaFuncAttributeMaxDynamicSharedMemorySize, SMEM128);

    // 0. pre-round all GEMM operands to tf32 (rna) once
    pack_w_kernel<<<(3 * D * D + 255) / 256, 256>>>(WQ, WK, WV);
    cvt_kernel<<<(S * D / 4 + 255) / 256, 256>>>(X, Xc, S * D / 4);
    cvt_kernel<<<(D * D / 4 + 255) / 256, 256>>>(WOw, WOc, D * D / 4);
    cvt_kernel<<<(DFF * D / 4 + 255) / 256, 256>>>(FF1w, FF1c, DFF * D / 4);
    cvt_kernel<<<(D * DFF / 4 + 255) / 256, 256>>>(FF2w, FF2c, D * DFF / 4);

    // 1. QKV projection: 128x256 tiles
    tf32gemm_ca<256, 0><<<dim3(3 * D / 256, S / 128), 256, SMEM256>>>(
        Xc, WqkvT, nullptr, nullptr, QKV, nullptr, S, 3 * D, D);

    // 2. scores (+ALiBi, causal) into SA region (3xTF32, fp32-exact)
    scores_tc_kernel<<<dim3(S / 128, S / 128, H), 256>>>(QKV, SA);

    // 3. in-place softmax over causal prefix of each row
    softmax_kernel<<<H * S, 256>>>(SA);

    // 4. z = SA @ V (tensor cores; writes tf32-rounded Z)
    av_tc_kernel<<<dim3(S / 128, H), 256>>>(SA, QKV, Z);

    // 5. attouts = X + Z @ WO_w^T ; writes fp32 ATT + rounded ATTc
    tf32gemm_ca<128, 3><<<dim3(D / 128, S / 128), 256, SMEM128>>>(
        Z, WOc, WOb, X, ATT, ATTc, S, D, D);

    // 6. H1 = tf32(relu(ATTc @ FF1_w^T + FF1_b)) : 128x256 tiles
    tf32gemm_ca<256, 2><<<dim3(DFF / 256, S / 128), 256, SMEM256>>>(
        ATTc, FF1c, FF1b, nullptr, H1, nullptr, S, DFF, D);

    // 7. out = ATT + H1 @ FF2_w^T + FF2_b
    tf32gemm_ca<128, 1><<<dim3(D / 128, S / 128), 256, SMEM128>>>(
        H1, FF2c, FF2b, ATT, OUT, nullptr, S, D, DFF);
}

// round 11
// speedup vs baseline: 1.0603x; 1.0603x over previous
#include <cuda_runtime.h>
#include <cstdint>

// Problem constants
#define S 2048
#define D 1024
#define H 16
#define DI 64
#define DV 64
#define DFF 4096
#define SA_ELEMS ((size_t)H * S * S)   // 67108864

// -------------------- scratch (device globals) -----------------------------
__device__ float g_WqkvT[(size_t)(3 * D) * D];   // packed transposed, tf32-rounded
__device__ float g_QKV[(size_t)S * 3 * D];       // [S, 3072] full fp32
__device__ float g_Z[(size_t)S * D];             // tf32-rounded (av epilogue)
__device__ float g_ATT[(size_t)S * D];           // full fp32 (residual)
__device__ float g_ATTc[(size_t)S * D];          // tf32-rounded copy
__device__ float g_H1[(size_t)S * DFF];          // tf32-rounded (FF1 epilogue)
__device__ float g_Xc[(size_t)S * D];            // tf32-rounded input
__device__ float g_WOc[(size_t)D * D];           // tf32-rounded WO_w
__device__ float g_FF1c[(size_t)DFF * D];        // tf32-rounded FF1_w
__device__ float g_FF2c[(size_t)D * DFF];        // tf32-rounded FF2_w
__device__ float g_part[(size_t)H * S * 16];     // per-(row, jt-block) exp sums
__device__ float g_invsum[(size_t)H * S];        // 1 / row sum of exp

// -------------------- helpers ---------------------------------------------
__device__ __forceinline__ unsigned f2tf32(float x) {
    unsigned u;
    asm("cvt.rna.tf32.f32 %0, %1;" : "=r"(u) : "f"(x));
    return u;
}
__device__ __forceinline__ float f2tf32f(float x) { return __uint_as_float(f2tf32(x)); }

__device__ __forceinline__ float4 cvt4(float4 v) {
    float4 t;
    t.x = f2tf32f(v.x); t.y = f2tf32f(v.y);
    t.z = f2tf32f(v.z); t.w = f2tf32f(v.w);
    return t;
}

__device__ __forceinline__ void ldsm_x4(unsigned& r0, unsigned& r1, unsigned& r2, unsigned& r3,
                                        const float* p) {
    unsigned addr = (unsigned)__cvta_generic_to_shared(p);
    asm volatile("ldmatrix.sync.aligned.m8n8.x4.shared.b16 {%0,%1,%2,%3}, [%4];"
                 : "=r"(r0), "=r"(r1), "=r"(r2), "=r"(r3) : "r"(addr));
}

__device__ __forceinline__ void mma_tf32(float* c, const unsigned* a, const unsigned* b) {
    asm volatile(
        "mma.sync.aligned.m16n8k8.row.col.f32.tf32.tf32.f32 "
        "{%0,%1,%2,%3}, {%4,%5,%6,%7}, {%8,%9}, {%0,%1,%2,%3};"
        : "+f"(c[0]), "+f"(c[1]), "+f"(c[2]), "+f"(c[3])
        : "r"(a[0]), "r"(a[1]), "r"(a[2]), "r"(a[3]), "r"(b[0]), "r"(b[1]));
}

__device__ __forceinline__ void cp_async16(float* smem_dst, const float* gsrc) {
    unsigned dst = (unsigned)__cvta_generic_to_shared(smem_dst);
    asm volatile("cp.async.cg.shared.global [%0], [%1], 16;" :: "r"(dst), "l"(gsrc));
}
__device__ __forceinline__ void cp_commit() {
    asm volatile("cp.async.commit_group;");
}
template <int N>
__device__ __forceinline__ void cp_wait() {
    asm volatile("cp.async.wait_group %0;" :: "n"(N));
}

// -------------------- elementwise tf32 round (pre-convert) -----------------
__global__ void cvt_kernel(const float* __restrict__ in, float* __restrict__ out, int n4) {
    int i = blockIdx.x * 256 + threadIdx.x;
    if (i >= n4) return;
    float4 v = *(const float4*)(in + (size_t)i * 4);
    *(float4*)(out + (size_t)i * 4) = cvt4(v);
}

// -------------------- pack WQ/WK/WV transposed + round: [3072, 1024] -------
__global__ void pack_w_kernel(const float* __restrict__ WQ,
                              const float* __restrict__ WK,
                              const float* __restrict__ WV) {
    int idx = blockIdx.x * 256 + threadIdx.x;   // n*1024 + d
    if (idx >= 3 * D * D) return;
    int d = idx & 1023;
    int n = idx >> 10;
    int sect = n >> 10;
    int nn = n & 1023;
    int h = nn >> 6, e = nn & 63;
    const float* W = (sect == 0) ? WQ : (sect == 1) ? WK : WV;
    g_WqkvT[idx] = f2tf32f(W[((size_t)h * D + d) * 64 + e]);
}

// ---- tf32 GEMM, cp.async 3-stage, 128x128 tiles: C = A[MxK]*B[NxK]^T ------
// Operands must be tf32-pre-rounded in gmem.
// EPI: 0 = write C
//      1 = C = acc + bias[n] + res[m,n]
//      2 = C = tf32(relu(acc + bias[n]))
//      3 = C = acc + bias[n] + res[m,n], C2 = tf32(C)
template <int EPI>
__global__ __launch_bounds__(256)
void tf32gemm_ca(const float* __restrict__ A, const float* __restrict__ B,
                 const float* __restrict__ bias, const float* __restrict__ res,
                 float* __restrict__ C, float* __restrict__ C2,
                 int M, int N, int K) {
    const int BM = 128, BK = 16, LDS_ = 20, STG = 3;
    extern __shared__ float smemf[];
    float* As = smemf;                       // STG stages of BM*LDS_
    float* Bs = smemf + STG * BM * LDS_;

    int tid = threadIdx.x;
    int lane = tid & 31, warp = tid >> 5;
    int warpM = warp >> 1, warpN = warp & 1;     // 4 x 2 warp grid
    int bm = blockIdx.y * BM, bn = blockIdx.x * BM;

    float acc[2][8][4];
#pragma unroll
    for (int i = 0; i < 2; i++)
#pragma unroll
        for (int j = 0; j < 8; j++)
#pragma unroll
            for (int r = 0; r < 4; r++) acc[i][j][r] = 0.f;

    int a_row = warpM * 32 + (lane & 15);
    int a_col = (lane >> 4) * 4;
    int b_row = warpN * 64 + (lane & 7) + ((lane >> 4) << 3);
    int b_col = ((lane >> 3) & 1) * 4;

    int ld_r = tid >> 2, ld_c4 = (tid & 3) * 4;
    const float* Ap = A + (size_t)(bm + ld_r) * K + ld_c4;
    const float* Bp = B + (size_t)(bn + ld_r) * K + ld_c4;
    size_t rowoff = (size_t)64 * K;

    int nk = K / BK;

    // prologue: stages 0..STG-2
#pragma unroll
    for (int s = 0; s < STG - 1; s++) {
        float* Asb = As + s * BM * LDS_;
        float* Bsb = Bs + s * BM * LDS_;
        const float* Ak = Ap + (size_t)s * BK;
        const float* Bk = Bp + (size_t)s * BK;
        cp_async16(Asb + ld_r * LDS_ + ld_c4, Ak);
        cp_async16(Asb + (ld_r + 64) * LDS_ + ld_c4, Ak + rowoff);
        cp_async16(Bsb + ld_r * LDS_ + ld_c4, Bk);
        cp_async16(Bsb + (ld_r + 64) * LDS_ + ld_c4, Bk + rowoff);
        cp_commit();
    }

    for (int kt = 0; kt < nk; kt++) {
        cp_wait<STG - 2>();
        __syncthreads();

        if (kt + STG - 1 < nk) {
            int s = (kt + STG - 1) % STG;
            float* Asb = As + s * BM * LDS_;
            float* Bsb = Bs + s * BM * LDS_;
            const float* Ak = Ap + (size_t)(kt + STG - 1) * BK;
            const float* Bk = Bp + (size_t)(kt + STG - 1) * BK;
            cp_async16(Asb + ld_r * LDS_ + ld_c4, Ak);
            cp_async16(Asb + (ld_r + 64) * LDS_ + ld_c4, Ak + rowoff);
            cp_async16(Bsb + ld_r * LDS_ + ld_c4, Bk);
            cp_async16(Bsb + (ld_r + 64) * LDS_ + ld_c4, Bk + rowoff);
            cp_commit();
        }

        const float* Asb = As + (kt % STG) * BM * LDS_;
        const float* Bsb = Bs + (kt % STG) * BM * LDS_;
#pragma unroll
        for (int ks = 0; ks < 2; ks++) {
            unsigned af[2][4];
            unsigned bf[8][2];
#pragma unroll
            for (int mt = 0; mt < 2; mt++) {
                ldsm_x4(af[mt][0], af[mt][1], af[mt][2], af[mt][3],
                        &Asb[(a_row + mt * 16) * LDS_ + ks * 8 + a_col]);
            }
#pragma unroll
            for (int np = 0; np < 4; np++) {
                ldsm_x4(bf[2 * np][0], bf[2 * np][1], bf[2 * np + 1][0], bf[2 * np + 1][1],
                        &Bsb[(b_row + np * 16) * LDS_ + ks * 8 + b_col]);
            }
#pragma unroll
            for (int mt = 0; mt < 2; mt++)
#pragma unroll
                for (int nt = 0; nt < 8; nt++)
                    mma_tf32(acc[mt][nt], af[mt], bf[nt]);
        }
        __syncthreads();
    }

    int g = lane >> 2, c2 = (lane & 3) * 2;
#pragma unroll
    for (int mt = 0; mt < 2; mt++) {
#pragma unroll
        for (int half = 0; half < 2; half++) {
            int m = bm + warpM * 32 + mt * 16 + g + half * 8;
#pragma unroll
            for (int nt = 0; nt < 8; nt++) {
                int n = bn + warpN * 64 + nt * 8 + c2;
                float v0 = acc[mt][nt][half * 2 + 0];
                float v1 = acc[mt][nt][half * 2 + 1];
                if (EPI >= 1) { v0 += bias[n]; v1 += bias[n + 1]; }
                if (EPI == 1 || EPI == 3) {
                    float2 rr = *(const float2*)(res + (size_t)m * N + n);
                    v0 += rr.x; v1 += rr.y;
                }
                if (EPI == 2) {
                    v0 = f2tf32f(fmaxf(v0, 0.f));
                    v1 = f2tf32f(fmaxf(v1, 0.f));
                }
                float2 o; o.x = v0; o.y = v1;
                *(float2*)(C + (size_t)m * N + n) = o;
                if (EPI == 3) {
                    float2 oc; oc.x = f2tf32f(v0); oc.y = f2tf32f(v1);
                    *(float2*)(C2 + (size_t)m * N + n) = oc;
                }
            }
        }
    }
}

// ---- scores: write e = exp(QK/8 - alibi) (0 above diag) + row-sum partials -
__global__ __launch_bounds__(256)
void scores_tc_kernel(const float* __restrict__ QKV, float* __restrict__ SA) {
    const int LDS_ = 20;
    int jt = blockIdx.x, it = blockIdx.y, h = blockIdx.z;
    int bm = it * 128, bn = jt * 128;
    float* out = SA + ((size_t)h * S + bm) * S + bn;
    int tid = threadIdx.x;

    if (jt > it) {   // strictly above diagonal at 128-granularity: zeros
#pragma unroll
        for (int r = 0; r < 16; r++) {
            int id = tid + r * 256;
            int row = id >> 5, c4 = (id & 31) * 4;
            *(float4*)(out + (size_t)row * S + c4) = make_float4(0.f, 0.f, 0.f, 0.f);
        }
        return;
    }

    __shared__ float Qh[128 * LDS_], Ql[128 * LDS_];
    __shared__ float Kh[128 * LDS_], Kl[128 * LDS_];
    __shared__ float blksum[128];

    int lane = tid & 31, warp = tid >> 5;
    int warpM = warp >> 1, warpN = warp & 1;

    if (tid < 128) blksum[tid] = 0.f;

    float acc[2][8][4];
#pragma unroll
    for (int i = 0; i < 2; i++)
#pragma unroll
        for (int j = 0; j < 8; j++)
#pragma unroll
            for (int r = 0; r < 4; r++) acc[i][j][r] = 0.f;

    int a_row = warpM * 32 + (lane & 15);
    int a_col = (lane >> 4) * 4;
    int b_row = warpN * 64 + (lane & 7) + ((lane >> 4) << 3);
    int b_col = ((lane >> 3) & 1) * 4;

    const float* Qb = QKV + (size_t)bm * (3 * D) + h * 64;
    const float* Kb = QKV + (size_t)bn * (3 * D) + D + h * 64;

    for (int kc = 0; kc < 4; kc++) {
#pragma unroll
        for (int i = 0; i < 2; i++) {
            int id = tid + i * 256;
            int row = id >> 2, c4 = (id & 3) * 4;
            float4 q = *(const float4*)(Qb + (size_t)row * (3 * D) + kc * 16 + c4);
            float4 k = *(const float4*)(Kb + (size_t)row * (3 * D) + kc * 16 + c4);
            float4 qh = cvt4(q), kh = cvt4(k);
            float4 ql, kl;
            ql.x = f2tf32f(q.x - qh.x); ql.y = f2tf32f(q.y - qh.y);
            ql.z = f2tf32f(q.z - qh.z); ql.w = f2tf32f(q.w - qh.w);
            kl.x = f2tf32f(k.x - kh.x); kl.y = f2tf32f(k.y - kh.y);
            kl.z = f2tf32f(k.z - kh.z); kl.w = f2tf32f(k.w - kh.w);
            *(float4*)&Qh[row * LDS_ + c4] = qh;
            *(float4*)&Ql[row * LDS_ + c4] = ql;
            *(float4*)&Kh[row * LDS_ + c4] = kh;
            *(float4*)&Kl[row * LDS_ + c4] = kl;
        }
        __syncthreads();

#pragma unroll
        for (int ks = 0; ks < 2; ks++) {
            unsigned afh[2][4], afl[2][4];
            unsigned bfh[8][2], bfl[8][2];
#pragma unroll
            for (int mt = 0; mt < 2; mt++) {
                ldsm_x4(afh[mt][0], afh[mt][1], afh[mt][2], afh[mt][3],
                        &Qh[(a_row + mt * 16) * LDS_ + ks * 8 + a_col]);
                ldsm_x4(afl[mt][0], afl[mt][1], afl[mt][2], afl[mt][3],
                        &Ql[(a_row + mt * 16) * LDS_ + ks * 8 + a_col]);
            }
#pragma unroll
            for (int np = 0; np < 4; np++) {
                ldsm_x4(bfh[2 * np][0], bfh[2 * np][1], bfh[2 * np + 1][0], bfh[2 * np + 1][1],
                        &Kh[(b_row + np * 16) * LDS_ + ks * 8 + b_col]);
                ldsm_x4(bfl[2 * np][0], bfl[2 * np][1], bfl[2 * np + 1][0], bfl[2 * np + 1][1],
                        &Kl[(b_row + np * 16) * LDS_ + ks * 8 + b_col]);
            }
#pragma unroll
            for (int mt = 0; mt < 2; mt++)
#pragma unroll
                for (int nt = 0; nt < 8; nt++) {
                    mma_tf32(acc[mt][nt], afh[mt], bfh[nt]);
                    mma_tf32(acc[mt][nt], afh[mt], bfl[nt]);
                    mma_tf32(acc[mt][nt], afl[mt], bfh[nt]);
                }
        }
        __syncthreads();
    }

    float slope = exp2f(-0.5f * (float)(h + 1));
    int g = lane >> 2, c2 = (lane & 3) * 2;
#pragma unroll
    for (int mt = 0; mt < 2; mt++) {
#pragma unroll
        for (int half = 0; half < 2; half++) {
            int li = warpM * 32 + mt * 16 + g + half * 8;
            int gi = bm + li;
            float rs = 0.f;
#pragma unroll
            for (int nt = 0; nt < 8; nt++) {
                int lj = warpN * 64 + nt * 8 + c2;
                int gj = bn + lj;
                float v0 = acc[mt][nt][half * 2 + 0];
                float v1 = acc[mt][nt][half * 2 + 1];
                float e0 = (gj <= gi)
                    ? __expf(v0 * 0.125f - (float)(gi - gj) * slope) : 0.f;
                float e1 = (gj + 1 <= gi)
                    ? __expf(v1 * 0.125f - (float)(gi - gj - 1) * slope) : 0.f;
                rs += e0 + e1;
                float2 o; o.x = e0; o.y = e1;
                *(float2*)(out + (size_t)li * S + lj) = o;
            }
            // reduce across 4 lanes owning the same row (c2 varies)
            rs += __shfl_xor_sync(0xffffffffu, rs, 1);
            rs += __shfl_xor_sync(0xffffffffu, rs, 2);
            if ((lane & 3) == 0) atomicAdd(&blksum[li], rs);
        }
    }
    __syncthreads();
    if (tid < 128)
        g_part[((size_t)h * S + bm + tid) * 16 + jt] = blksum[tid];
}

// ---- deterministic row-sum reduce: invsum[h*S+i] = 1/sum_jt part ----------
__global__ void rowsum_reduce_kernel() {
    int idx = blockIdx.x * 256 + threadIdx.x;   // over H*S
    if (idx >= H * S) return;
    int gi = idx & (S - 1);
    int it = gi >> 7;
    const float* p = g_part + (size_t)idx * 16;
    float s = 0.f;
    for (int j = 0; j <= it; j++) s += p[j];
    g_invsum[idx] = 1.f / s;
}

// ---- av: p = e*invsum; write p back to SA; z = p @ V (tensor cores) -------
__global__ __launch_bounds__(256)
void av_tc_kernel(float* __restrict__ SA, const float* __restrict__ QKV,
                  float* __restrict__ Z) {
    const int LDS_ = 20;
    int bi = blockIdx.x, h = blockIdx.y;
    int bm = bi * 128;
    int tid = threadIdx.x;
    int lane = tid & 31, warp = tid >> 5;

    __shared__ float SAs[128 * LDS_];
    __shared__ float Vs[64 * LDS_];

    float acc[8][4];
#pragma unroll
    for (int j = 0; j < 8; j++)
#pragma unroll
        for (int r = 0; r < 4; r++) acc[j][r] = 0.f;

    int a_row = warp * 16 + (lane & 15);
    int a_col = (lane >> 4) * 4;
    int b_row = (lane & 7) + ((lane >> 4) << 3);
    int b_col = ((lane >> 3) & 1) * 4;

    float* SAb = SA + ((size_t)h * S + bm) * S;
    const float* Vb = QKV + 2 * D + (size_t)h * 64;

    int ldrow = tid >> 2;
    float inv0 = g_invsum[(size_t)h * S + bm + ldrow];
    float inv1 = g_invsum[(size_t)h * S + bm + ldrow + 64];

    int nchunks = (bm + 128) / 16;
    for (int kc = 0; kc < nchunks; kc++) {
        int k0 = kc * 16;
#pragma unroll
        for (int i = 0; i < 2; i++) {
            int id = tid + i * 256;
            int row = id >> 2, c4 = (id & 3) * 4;
            float inv = i ? inv1 : inv0;
            float* ap = SAb + (size_t)row * S + k0 + c4;
            float4 a = *(const float4*)ap;
            a.x *= inv; a.y *= inv; a.z *= inv; a.w *= inv;
            *(float4*)ap = a;                     // normalized prob to output
            *(float4*)&SAs[row * LDS_ + c4] = cvt4(a);
        }
        {
            int jloc = tid >> 6, v = tid & 63;
#pragma unroll
            for (int i = 0; i < 4; i++) {
                int jj = jloc + i * 4;
                float x = Vb[(size_t)(k0 + jj) * (3 * D) + v];
                Vs[v * LDS_ + jj] = f2tf32f(x);
            }
        }
        __syncthreads();

#pragma unroll
        for (int ks = 0; ks < 2; ks++) {
            unsigned af[4];
            unsigned bf[8][2];
            ldsm_x4(af[0], af[1], af[2], af[3],
                    &SAs[a_row * LDS_ + ks * 8 + a_col]);
#pragma unroll
            for (int np = 0; np < 4; np++) {
                ldsm_x4(bf[2 * np][0], bf[2 * np][1], bf[2 * np + 1][0], bf[2 * np + 1][1],
                        &Vs[(b_row + np * 16) * LDS_ + ks * 8 + b_col]);
            }
#pragma unroll
            for (int nt = 0; nt < 8; nt++)
                mma_tf32(acc[nt], af, bf[nt]);
        }
        __syncthreads();
    }

    int g = lane >> 2, c2 = (lane & 3) * 2;
#pragma unroll
    for (int half = 0; half < 2; half++) {
        int m = bm + warp * 16 + g + half * 8;
#pragma unroll
        for (int nt = 0; nt < 8; nt++) {
            int n = h * 64 + nt * 8 + c2;
            float2 o;
            o.x = f2tf32f(acc[nt][half * 2 + 0]);   // Z feeds only the WO GEMM
            o.y = f2tf32f(acc[nt][half * 2 + 1]);
            *(float2*)(Z + (size_t)m * D + n) = o;
        }
    }
}

// --------------------------- launch ---------------------------------------
extern "C" void kernel_launch(void* const* d_in, const int* in_sizes, int n_in,
                              void* d_out, int out_size) {
    const float* X    = (const float*)d_in[0];
    const float* WQ   = (const float*)d_in[1];
    const float* WK   = (const float*)d_in[2];
    const float* WV   = (const float*)d_in[3];
    const float* WOw  = (const float*)d_in[4];
    const float* WOb  = (const float*)d_in[5];
    const float* FF1w = (const float*)d_in[6];
    const float* FF1b = (const float*)d_in[7];
    const float* FF2w = (const float*)d_in[8];
    const float* FF2b = (const float*)d_in[9];

    float* SA  = (float*)d_out;
    float* OUT = (float*)d_out + SA_ELEMS;

    float *WqkvT, *QKV, *Z, *ATT, *ATTc, *H1, *Xc, *WOc, *FF1c, *FF2c;
    cudaGetSymbolAddress((void**)&WqkvT, g_WqkvT);
    cudaGetSymbolAddress((void**)&QKV, g_QKV);
    cudaGetSymbolAddress((void**)&Z, g_Z);
    cudaGetSymbolAddress((void**)&ATT, g_ATT);
    cudaGetSymbolAddress((void**)&ATTc, g_ATTc);
    cudaGetSymbolAddress((void**)&H1, g_H1);
    cudaGetSymbolAddress((void**)&Xc, g_Xc);
    cudaGetSymbolAddress((void**)&WOc, g_WOc);
    cudaGetSymbolAddress((void**)&FF1c, g_FF1c);
    cudaGetSymbolAddress((void**)&FF2c, g_FF2c);

    // dynamic smem: 3 stages x 256 rows x 20 floats
    const int SMEMG = 3 * 256 * 20 * 4;   // 61440
    cudaFuncSetAttribute(tf32gemm_ca<0>, cudaFuncAttributeMaxDynamicSharedMemorySize, SMEMG);
    cudaFuncSetAttribute(tf32gemm_ca<1>, cudaFuncAttributeMaxDynamicSharedMemorySize, SMEMG);
    cudaFuncSetAttribute(tf32gemm_ca<2>, cudaFuncAttributeMaxDynamicSharedMemorySize, SMEMG);
    cudaFuncSetAttribute(tf32gemm_ca<3>, cudaFuncAttributeMaxDynamicSharedMemorySize, SMEMG);

    // 0. pre-round all GEMM operands to tf32 (rna) once
    pack_w_kernel<<<(3 * D * D + 255) / 256, 256>>>(WQ, WK, WV);
    cvt_kernel<<<(S * D / 4 + 255) / 256, 256>>>(X, Xc, S * D / 4);
    cvt_kernel<<<(D * D / 4 + 255) / 256, 256>>>(WOw, WOc, D * D / 4);
    cvt_kernel<<<(DFF * D / 4 + 255) / 256, 256>>>(FF1w, FF1c, DFF * D / 4);
    cvt_kernel<<<(D * DFF / 4 + 255) / 256, 256>>>(FF2w, FF2c, D * DFF / 4);

    // 1. QKV projection
    tf32gemm_ca<0><<<dim3(3 * D / 128, S / 128), 256, SMEMG>>>(
        Xc, WqkvT, nullptr, nullptr, QKV, nullptr, S, 3 * D, D);

    // 2. scores: e = exp(QK/8 - alibi) into SA + row-sum partials
    scores_tc_kernel<<<dim3(S / 128, S / 128, H), 256>>>(QKV, SA);

    // 3. deterministic row-sum reduction -> invsum
    rowsum_reduce_kernel<<<(H * S + 255) / 256, 256>>>();

    // 4. av: normalize SA in-place (write probs) and z = p @ V
    av_tc_kernel<<<dim3(S / 128, H), 256>>>(SA, QKV, Z);

    // 5. attouts = X + Z @ WO_w^T ; writes fp32 ATT + rounded ATTc
    tf32gemm_ca<3><<<dim3(D / 128, S / 128), 256, SMEMG>>>(
        Z, WOc, WOb, X, ATT, ATTc, S, D, D);

    // 6. H1 = tf32(relu(ATTc @ FF1_w^T + FF1_b))
    tf32gemm_ca<2><<<dim3(DFF / 128, S / 128), 256, SMEMG>>>(
        ATTc, FF1c, FF1b, nullptr, H1, nullptr, S, DFF, D);

    // 7. out = ATT + H1 @ FF2_w^T + FF2_b
    tf32gemm_ca<1><<<dim3(D / 128, S / 128), 256, SMEMG>>>(
        H1, FF2c, FF2b, ATT, OUT, nullptr, S, D, DFF);
}

// round 12
// speedup vs baseline: 1.2227x; 1.1531x over previous
#include <cuda_runtime.h>
#include <cstdint>

// Problem constants
#define S 2048
#define D 1024
#define H 16
#define DI 64
#define DV 64
#define DFF 4096
#define SA_ELEMS ((size_t)H * S * S)   // 67108864

// -------------------- scratch (device globals) -----------------------------
__device__ float g_WqkvT[(size_t)(3 * D) * D];   // packed transposed, tf32-rounded
__device__ float g_QKV[(size_t)S * 3 * D];       // [S, 3072] full fp32
__device__ float g_Z[(size_t)S * D];             // tf32-rounded (av epilogue)
__device__ float g_ATT[(size_t)S * D];           // full fp32 (residual)
__device__ float g_ATTc[(size_t)S * D];          // tf32-rounded copy
__device__ float g_H1[(size_t)S * DFF];          // tf32-rounded (FF1 epilogue)
__device__ float g_Xc[(size_t)S * D];            // tf32-rounded input
__device__ float g_WOc[(size_t)D * D];           // tf32-rounded WO_w
__device__ float g_FF1c[(size_t)DFF * D];        // tf32-rounded FF1_w
__device__ float g_FF2c[(size_t)D * DFF];        // tf32-rounded FF2_w
__device__ float g_part[(size_t)H * S * 16];     // per-(row, jt-block) exp sums
__device__ float g_invsum[(size_t)H * S];        // 1 / row sum of exp

// -------------------- helpers ---------------------------------------------
__device__ __forceinline__ unsigned f2tf32(float x) {
    unsigned u;
    asm("cvt.rna.tf32.f32 %0, %1;" : "=r"(u) : "f"(x));
    return u;
}
__device__ __forceinline__ float f2tf32f(float x) { return __uint_as_float(f2tf32(x)); }

__device__ __forceinline__ float4 cvt4(float4 v) {
    float4 t;
    t.x = f2tf32f(v.x); t.y = f2tf32f(v.y);
    t.z = f2tf32f(v.z); t.w = f2tf32f(v.w);
    return t;
}

__device__ __forceinline__ void ldsm_x4(unsigned& r0, unsigned& r1, unsigned& r2, unsigned& r3,
                                        const float* p) {
    unsigned addr = (unsigned)__cvta_generic_to_shared(p);
    asm volatile("ldmatrix.sync.aligned.m8n8.x4.shared.b16 {%0,%1,%2,%3}, [%4];"
                 : "=r"(r0), "=r"(r1), "=r"(r2), "=r"(r3) : "r"(addr));
}

__device__ __forceinline__ void mma_tf32(float* c, const unsigned* a, const unsigned* b) {
    asm volatile(
        "mma.sync.aligned.m16n8k8.row.col.f32.tf32.tf32.f32 "
        "{%0,%1,%2,%3}, {%4,%5,%6,%7}, {%8,%9}, {%0,%1,%2,%3};"
        : "+f"(c[0]), "+f"(c[1]), "+f"(c[2]), "+f"(c[3])
        : "r"(a[0]), "r"(a[1]), "r"(a[2]), "r"(a[3]), "r"(b[0]), "r"(b[1]));
}

__device__ __forceinline__ void cp_async16(float* smem_dst, const float* gsrc) {
    unsigned dst = (unsigned)__cvta_generic_to_shared(smem_dst);
    asm volatile("cp.async.cg.shared.global [%0], [%1], 16;" :: "r"(dst), "l"(gsrc));
}
__device__ __forceinline__ void cp_commit() {
    asm volatile("cp.async.commit_group;");
}
template <int N>
__device__ __forceinline__ void cp_wait() {
    asm volatile("cp.async.wait_group %0;" :: "n"(N));
}

// -------------------- elementwise tf32 round (pre-convert) -----------------
__global__ void cvt_kernel(const float* __restrict__ in, float* __restrict__ out, int n4) {
    int i = blockIdx.x * 256 + threadIdx.x;
    if (i >= n4) return;
    float4 v = *(const float4*)(in + (size_t)i * 4);
    *(float4*)(out + (size_t)i * 4) = cvt4(v);
}

// -------------------- pack WQ/WK/WV transposed + round: [3072, 1024] -------
__global__ void pack_w_kernel(const float* __restrict__ WQ,
                              const float* __restrict__ WK,
                              const float* __restrict__ WV) {
    int idx = blockIdx.x * 256 + threadIdx.x;   // n*1024 + d
    if (idx >= 3 * D * D) return;
    int d = idx & 1023;
    int n = idx >> 10;
    int sect = n >> 10;
    int nn = n & 1023;
    int h = nn >> 6, e = nn & 63;
    const float* W = (sect == 0) ? WQ : (sect == 1) ? WK : WV;
    g_WqkvT[idx] = f2tf32f(W[((size_t)h * D + d) * 64 + e]);
}

// ---- tf32 GEMM, cp.async 3-stage, BK=32, single barrier per K-step --------
// C = A[MxK]*B[NxK]^T ; operands tf32-pre-rounded in gmem.
// EPI: 0 = write C
//      1 = C = acc + bias[n] + res[m,n]
//      2 = C = tf32(relu(acc + bias[n]))
//      3 = C = acc + bias[n] + res[m,n], C2 = tf32(C)
template <int EPI>
__global__ __launch_bounds__(256, 2)
void tf32gemm_ca(const float* __restrict__ A, const float* __restrict__ B,
                 const float* __restrict__ bias, const float* __restrict__ res,
                 float* __restrict__ C, float* __restrict__ C2,
                 int M, int N, int K) {
    const int BM = 128, BK = 32, LDS_ = 36, STG = 3;
    extern __shared__ float smemf[];
    float* As = smemf;                       // STG stages of BM*LDS_
    float* Bs = smemf + STG * BM * LDS_;

    int tid = threadIdx.x;
    int lane = tid & 31, warp = tid >> 5;
    int warpM = warp >> 1, warpN = warp & 1;     // 4 x 2 warp grid
    int bm = blockIdx.y * BM, bn = blockIdx.x * BM;

    float acc[2][8][4];
#pragma unroll
    for (int i = 0; i < 2; i++)
#pragma unroll
        for (int j = 0; j < 8; j++)
#pragma unroll
            for (int r = 0; r < 4; r++) acc[i][j][r] = 0.f;

    int a_row = warpM * 32 + (lane & 15);
    int a_col = (lane >> 4) * 4;
    int b_row = warpN * 64 + (lane & 7) + ((lane >> 4) << 3);
    int b_col = ((lane >> 3) & 1) * 4;

    // load mapping: 32 rows x 32 cols per pass; 4 passes cover 128 rows
    int ld_r = tid >> 3, ld_c4 = (tid & 7) * 4;
    const float* Ap = A + (size_t)(bm + ld_r) * K + ld_c4;
    const float* Bp = B + (size_t)(bn + ld_r) * K + ld_c4;
    size_t rowoff = (size_t)32 * K;

    int nk = K / BK;

    // prologue: stages 0..STG-2
#pragma unroll
    for (int s = 0; s < STG - 1; s++) {
        float* Asb = As + s * BM * LDS_;
        float* Bsb = Bs + s * BM * LDS_;
        const float* Ak = Ap + (size_t)s * BK;
        const float* Bk = Bp + (size_t)s * BK;
#pragma unroll
        for (int i = 0; i < 4; i++) {
            cp_async16(Asb + (ld_r + i * 32) * LDS_ + ld_c4, Ak + i * rowoff);
            cp_async16(Bsb + (ld_r + i * 32) * LDS_ + ld_c4, Bk + i * rowoff);
        }
        cp_commit();
    }

    for (int kt = 0; kt < nk; kt++) {
        cp_wait<STG - 2>();
        __syncthreads();   // fences both arrival of stage kt and completion of reads of stage kt-1

        if (kt + STG - 1 < nk) {
            int s = (kt + STG - 1) % STG;
            float* Asb = As + s * BM * LDS_;
            float* Bsb = Bs + s * BM * LDS_;
            const float* Ak = Ap + (size_t)(kt + STG - 1) * BK;
            const float* Bk = Bp + (size_t)(kt + STG - 1) * BK;
#pragma unroll
            for (int i = 0; i < 4; i++) {
                cp_async16(Asb + (ld_r + i * 32) * LDS_ + ld_c4, Ak + i * rowoff);
                cp_async16(Bsb + (ld_r + i * 32) * LDS_ + ld_c4, Bk + i * rowoff);
            }
            cp_commit();
        }

        const float* Asb = As + (kt % STG) * BM * LDS_;
        const float* Bsb = Bs + (kt % STG) * BM * LDS_;
#pragma unroll
        for (int ks = 0; ks < 4; ks++) {
            unsigned af[2][4];
            unsigned bf[8][2];
#pragma unroll
            for (int mt = 0; mt < 2; mt++) {
                ldsm_x4(af[mt][0], af[mt][1], af[mt][2], af[mt][3],
                        &Asb[(a_row + mt * 16) * LDS_ + ks * 8 + a_col]);
            }
#pragma unroll
            for (int np = 0; np < 4; np++) {
                ldsm_x4(bf[2 * np][0], bf[2 * np][1], bf[2 * np + 1][0], bf[2 * np + 1][1],
                        &Bsb[(b_row + np * 16) * LDS_ + ks * 8 + b_col]);
            }
#pragma unroll
            for (int mt = 0; mt < 2; mt++)
#pragma unroll
                for (int nt = 0; nt < 8; nt++)
                    mma_tf32(acc[mt][nt], af[mt], bf[nt]);
        }
        // no trailing barrier: 3-stage rotation makes the top barrier sufficient
    }

    int g = lane >> 2, c2 = (lane & 3) * 2;
#pragma unroll
    for (int mt = 0; mt < 2; mt++) {
#pragma unroll
        for (int half = 0; half < 2; half++) {
            int m = bm + warpM * 32 + mt * 16 + g + half * 8;
#pragma unroll
            for (int nt = 0; nt < 8; nt++) {
                int n = bn + warpN * 64 + nt * 8 + c2;
                float v0 = acc[mt][nt][half * 2 + 0];
                float v1 = acc[mt][nt][half * 2 + 1];
                if (EPI >= 1) { v0 += bias[n]; v1 += bias[n + 1]; }
                if (EPI == 1 || EPI == 3) {
                    float2 rr = *(const float2*)(res + (size_t)m * N + n);
                    v0 += rr.x; v1 += rr.y;
                }
                if (EPI == 2) {
                    v0 = f2tf32f(fmaxf(v0, 0.f));
                    v1 = f2tf32f(fmaxf(v1, 0.f));
                }
                float2 o; o.x = v0; o.y = v1;
                *(float2*)(C + (size_t)m * N + n) = o;
                if (EPI == 3) {
                    float2 oc; oc.x = f2tf32f(v0); oc.y = f2tf32f(v1);
                    *(float2*)(C2 + (size_t)m * N + n) = oc;
                }
            }
        }
    }
}

// ---- scores: write e = exp(QK/8 - alibi) (0 above diag) + row-sum partials -
__global__ __launch_bounds__(256)
void scores_tc_kernel(const float* __restrict__ QKV, float* __restrict__ SA) {
    const int LDS_ = 20;
    int jt = blockIdx.x, it = blockIdx.y, h = blockIdx.z;
    int bm = it * 128, bn = jt * 128;
    float* out = SA + ((size_t)h * S + bm) * S + bn;
    int tid = threadIdx.x;

    if (jt > it) {   // strictly above diagonal at 128-granularity: zeros
#pragma unroll
        for (int r = 0; r < 16; r++) {
            int id = tid + r * 256;
            int row = id >> 5, c4 = (id & 31) * 4;
            *(float4*)(out + (size_t)row * S + c4) = make_float4(0.f, 0.f, 0.f, 0.f);
        }
        return;
    }

    __shared__ float Qh[128 * LDS_], Ql[128 * LDS_];
    __shared__ float Kh[128 * LDS_], Kl[128 * LDS_];
    __shared__ float blksum[128];

    int lane = tid & 31, warp = tid >> 5;
    int warpM = warp >> 1, warpN = warp & 1;

    if (tid < 128) blksum[tid] = 0.f;

    float acc[2][8][4];
#pragma unroll
    for (int i = 0; i < 2; i++)
#pragma unroll
        for (int j = 0; j < 8; j++)
#pragma unroll
            for (int r = 0; r < 4; r++) acc[i][j][r] = 0.f;

    int a_row = warpM * 32 + (lane & 15);
    int a_col = (lane >> 4) * 4;
    int b_row = warpN * 64 + (lane & 7) + ((lane >> 4) << 3);
    int b_col = ((lane >> 3) & 1) * 4;

    const float* Qb = QKV + (size_t)bm * (3 * D) + h * 64;
    const float* Kb = QKV + (size_t)bn * (3 * D) + D + h * 64;

    for (int kc = 0; kc < 4; kc++) {
#pragma unroll
        for (int i = 0; i < 2; i++) {
            int id = tid + i * 256;
            int row = id >> 2, c4 = (id & 3) * 4;
            float4 q = *(const float4*)(Qb + (size_t)row * (3 * D) + kc * 16 + c4);
            float4 k = *(const float4*)(Kb + (size_t)row * (3 * D) + kc * 16 + c4);
            float4 qh = cvt4(q), kh = cvt4(k);
            float4 ql, kl;
            ql.x = f2tf32f(q.x - qh.x); ql.y = f2tf32f(q.y - qh.y);
            ql.z = f2tf32f(q.z - qh.z); ql.w = f2tf32f(q.w - qh.w);
            kl.x = f2tf32f(k.x - kh.x); kl.y = f2tf32f(k.y - kh.y);
            kl.z = f2tf32f(k.z - kh.z); kl.w = f2tf32f(k.w - kh.w);
            *(float4*)&Qh[row * LDS_ + c4] = qh;
            *(float4*)&Ql[row * LDS_ + c4] = ql;
            *(float4*)&Kh[row * LDS_ + c4] = kh;
            *(float4*)&Kl[row * LDS_ + c4] = kl;
        }
        __syncthreads();

#pragma unroll
        for (int ks = 0; ks < 2; ks++) {
            unsigned afh[2][4], afl[2][4];
            unsigned bfh[8][2], bfl[8][2];
#pragma unroll
            for (int mt = 0; mt < 2; mt++) {
                ldsm_x4(afh[mt][0], afh[mt][1], afh[mt][2], afh[mt][3],
                        &Qh[(a_row + mt * 16) * LDS_ + ks * 8 + a_col]);
                ldsm_x4(afl[mt][0], afl[mt][1], afl[mt][2], afl[mt][3],
                        &Ql[(a_row + mt * 16) * LDS_ + ks * 8 + a_col]);
            }
#pragma unroll
            for (int np = 0; np < 4; np++) {
                ldsm_x4(bfh[2 * np][0], bfh[2 * np][1], bfh[2 * np + 1][0], bfh[2 * np + 1][1],
                        &Kh[(b_row + np * 16) * LDS_ + ks * 8 + b_col]);
                ldsm_x4(bfl[2 * np][0], bfl[2 * np][1], bfl[2 * np + 1][0], bfl[2 * np + 1][1],
                        &Kl[(b_row + np * 16) * LDS_ + ks * 8 + b_col]);
            }
#pragma unroll
            for (int mt = 0; mt < 2; mt++)
#pragma unroll
                for (int nt = 0; nt < 8; nt++) {
                    mma_tf32(acc[mt][nt], afh[mt], bfh[nt]);
                    mma_tf32(acc[mt][nt], afh[mt], bfl[nt]);
                    mma_tf32(acc[mt][nt], afl[mt], bfh[nt]);
                }
        }
        __syncthreads();
    }

    float slope = exp2f(-0.5f * (float)(h + 1));
    int g = lane >> 2, c2 = (lane & 3) * 2;
#pragma unroll
    for (int mt = 0; mt < 2; mt++) {
#pragma unroll
        for (int half = 0; half < 2; half++) {
            int li = warpM * 32 + mt * 16 + g + half * 8;
            int gi = bm + li;
            float rs = 0.f;
#pragma unroll
            for (int nt = 0; nt < 8; nt++) {
                int lj = warpN * 64 + nt * 8 + c2;
                int gj = bn + lj;
                float v0 = acc[mt][nt][half * 2 + 0];
                float v1 = acc[mt][nt][half * 2 + 1];
                float e0 = (gj <= gi)
                    ? __expf(v0 * 0.125f - (float)(gi - gj) * slope) : 0.f;
                float e1 = (gj + 1 <= gi)
                    ? __expf(v1 * 0.125f - (float)(gi - gj - 1) * slope) : 0.f;
                rs += e0 + e1;
                float2 o; o.x = e0; o.y = e1;
                *(float2*)(out + (size_t)li * S + lj) = o;
            }
            rs += __shfl_xor_sync(0xffffffffu, rs, 1);
            rs += __shfl_xor_sync(0xffffffffu, rs, 2);
            if ((lane & 3) == 0) atomicAdd(&blksum[li], rs);
        }
    }
    __syncthreads();
    if (tid < 128)
        g_part[((size_t)h * S + bm + tid) * 16 + jt] = blksum[tid];
}

// ---- deterministic row-sum reduce: invsum[h*S+i] = 1/sum_jt part ----------
__global__ void rowsum_reduce_kernel() {
    int idx = blockIdx.x * 256 + threadIdx.x;   // over H*S
    if (idx >= H * S) return;
    int gi = idx & (S - 1);
    int it = gi >> 7;
    const float* p = g_part + (size_t)idx * 16;
    float s = 0.f;
    for (int j = 0; j <= it; j++) s += p[j];
    g_invsum[idx] = 1.f / s;
}

// ---- av: p = e*invsum; write p back to SA; z = p @ V (double-buffered) ----
__global__ __launch_bounds__(256)
void av_tc_kernel(float* __restrict__ SA, const float* __restrict__ QKV,
                  float* __restrict__ Z) {
    const int LDS_ = 20;
    int bi = blockIdx.x, h = blockIdx.y;
    int bm = bi * 128;
    int tid = threadIdx.x;
    int lane = tid & 31, warp = tid >> 5;

    __shared__ float SAs[2][128 * LDS_];
    __shared__ float Vs[2][64 * LDS_];

    float acc[8][4];
#pragma unroll
    for (int j = 0; j < 8; j++)
#pragma unroll
        for (int r = 0; r < 4; r++) acc[j][r] = 0.f;

    int a_row = warp * 16 + (lane & 15);
    int a_col = (lane >> 4) * 4;
    int b_row = (lane & 7) + ((lane >> 4) << 3);
    int b_col = ((lane >> 3) & 1) * 4;

    float* SAb = SA + ((size_t)h * S + bm) * S;
    const float* Vb = QKV + 2 * D + (size_t)h * 64;

    int ldrow = tid >> 2, ld_c4 = (tid & 3) * 4;
    float inv0 = g_invsum[(size_t)h * S + bm + ldrow];
    float inv1 = g_invsum[(size_t)h * S + bm + ldrow + 64];
    int jloc = tid >> 6, vcol = tid & 63;

    int nchunks = (bm + 128) / 16;

    float4 ra0, ra1;
    float rv[4];

    // prologue: load + store chunk 0
    {
        ra0 = *(const float4*)(SAb + (size_t)ldrow * S + ld_c4);
        ra1 = *(const float4*)(SAb + (size_t)(ldrow + 64) * S + ld_c4);
#pragma unroll
        for (int i = 0; i < 4; i++)
            rv[i] = Vb[(size_t)(jloc + i * 4) * (3 * D) + vcol];

        ra0.x *= inv0; ra0.y *= inv0; ra0.z *= inv0; ra0.w *= inv0;
        ra1.x *= inv1; ra1.y *= inv1; ra1.z *= inv1; ra1.w *= inv1;
        *(float4*)(SAb + (size_t)ldrow * S + ld_c4) = ra0;
        *(float4*)(SAb + (size_t)(ldrow + 64) * S + ld_c4) = ra1;
        *(float4*)&SAs[0][ldrow * LDS_ + ld_c4] = cvt4(ra0);
        *(float4*)&SAs[0][(ldrow + 64) * LDS_ + ld_c4] = cvt4(ra1);
#pragma unroll
        for (int i = 0; i < 4; i++)
            Vs[0][vcol * LDS_ + jloc + i * 4] = f2tf32f(rv[i]);
    }
    __syncthreads();

    for (int kc = 0; kc < nchunks; kc++) {
        int buf = kc & 1;
        bool more = (kc + 1) < nchunks;

        if (more) {   // prefetch chunk kc+1 into registers
            int k0 = (kc + 1) * 16;
            ra0 = *(const float4*)(SAb + (size_t)ldrow * S + k0 + ld_c4);
            ra1 = *(const float4*)(SAb + (size_t)(ldrow + 64) * S + k0 + ld_c4);
#pragma unroll
            for (int i = 0; i < 4; i++)
                rv[i] = Vb[(size_t)(k0 + jloc + i * 4) * (3 * D) + vcol];
        }

#pragma unroll
        for (int ks = 0; ks < 2; ks++) {
            unsigned af[4];
            unsigned bf[8][2];
            ldsm_x4(af[0], af[1], af[2], af[3],
                    &SAs[buf][a_row * LDS_ + ks * 8 + a_col]);
#pragma unroll
            for (int np = 0; np < 4; np++) {
                ldsm_x4(bf[2 * np][0], bf[2 * np][1], bf[2 * np + 1][0], bf[2 * np + 1][1],
                        &Vs[buf][(b_row + np * 16) * LDS_ + ks * 8 + b_col]);
            }
#pragma unroll
            for (int nt = 0; nt < 8; nt++)
                mma_tf32(acc[nt], af, bf[nt]);
        }

        if (more) {   // scale, write back to gmem, store smem for next iter
            int k0 = (kc + 1) * 16;
            int nb = buf ^ 1;
            ra0.x *= inv0; ra0.y *= inv0; ra0.z *= inv0; ra0.w *= inv0;
            ra1.x *= inv1; ra1.y *= inv1; ra1.z *= inv1; ra1.w *= inv1;
            *(float4*)(SAb + (size_t)ldrow * S + k0 + ld_c4) = ra0;
            *(float4*)(SAb + (size_t)(ldrow + 64) * S + k0 + ld_c4) = ra1;
            *(float4*)&SAs[nb][ldrow * LDS_ + ld_c4] = cvt4(ra0);
            *(float4*)&SAs[nb][(ldrow + 64) * LDS_ + ld_c4] = cvt4(ra1);
#pragma unroll
            for (int i = 0; i < 4; i++)
                Vs[nb][vcol * LDS_ + jloc + i * 4] = f2tf32f(rv[i]);
            __syncthreads();
        }
    }

    int g = lane >> 2, c2 = (lane & 3) * 2;
#pragma unroll
    for (int half = 0; half < 2; half++) {
        int m = bm + warp * 16 + g + half * 8;
#pragma unroll
        for (int nt = 0; nt < 8; nt++) {
            int n = h * 64 + nt * 8 + c2;
            float2 o;
            o.x = f2tf32f(acc[nt][half * 2 + 0]);   // Z feeds only the WO GEMM
            o.y = f2tf32f(acc[nt][half * 2 + 1]);
            *(float2*)(Z + (size_t)m * D + n) = o;
        }
    }
}

// --------------------------- launch ---------------------------------------
extern "C" void kernel_launch(void* const* d_in, const int* in_sizes, int n_in,
                              void* d_out, int out_size) {
    const float* X    = (const float*)d_in[0];
    const float* WQ   = (const float*)d_in[1];
    const float* WK   = (const float*)d_in[2];
    const float* WV   = (const float*)d_in[3];
    const float* WOw  = (const float*)d_in[4];
    const float* WOb  = (const float*)d_in[5];
    const float* FF1w = (const float*)d_in[6];
    const float* FF1b = (const float*)d_in[7];
    const float* FF2w = (const float*)d_in[8];
    const float* FF2b = (const float*)d_in[9];

    float* SA  = (float*)d_out;
    float* OUT = (float*)d_out + SA_ELEMS;

    float *WqkvT, *QKV, *Z, *ATT, *ATTc, *H1, *Xc, *WOc, *FF1c, *FF2c;
    cudaGetSymbolAddress((void**)&WqkvT, g_WqkvT);
    cudaGetSymbolAddress((void**)&QKV, g_QKV);
    cudaGetSymbolAddress((void**)&Z, g_Z);
    cudaGetSymbolAddress((void**)&ATT, g_ATT);
    cudaGetSymbolAddress((void**)&ATTc, g_ATTc);
    cudaGetSymbolAddress((void**)&H1, g_H1);
    cudaGetSymbolAddress((void**)&Xc, g_Xc);
    cudaGetSymbolAddress((void**)&WOc, g_WOc);
    cudaGetSymbolAddress((void**)&FF1c, g_FF1c);
    cudaGetSymbolAddress((void**)&FF2c, g_FF2c);

    // dynamic smem: 3 stages x 256 rows x 36 floats = 110592 B
    const int SMEMG = 3 * 256 * 36 * 4;
    cudaFuncSetAttribute(tf32gemm_ca<0>, cudaFuncAttributeMaxDynamicSharedMemorySize, SMEMG);
    cudaFuncSetAttribute(tf32gemm_ca<1>, cudaFuncAttributeMaxDynamicSharedMemorySize, SMEMG);
    cudaFuncSetAttribute(tf32gemm_ca<2>, cudaFuncAttributeMaxDynamicSharedMemorySize, SMEMG);
    cudaFuncSetAttribute(tf32gemm_ca<3>, cudaFuncAttributeMaxDynamicSharedMemorySize, SMEMG);

    // 0. pre-round all GEMM operands to tf32 (rna) once
    pack_w_kernel<<<(3 * D * D + 255) / 256, 256>>>(WQ, WK, WV);
    cvt_kernel<<<(S * D / 4 + 255) / 256, 256>>>(X, Xc, S * D / 4);
    cvt_kernel<<<(D * D / 4 + 255) / 256, 256>>>(WOw, WOc, D * D / 4);
    cvt_kernel<<<(DFF * D / 4 + 255) / 256, 256>>>(FF1w, FF1c, DFF * D / 4);
    cvt_kernel<<<(D * DFF / 4 + 255) / 256, 256>>>(FF2w, FF2c, D * DFF / 4);

    // 1. QKV projection
    tf32gemm_ca<0><<<dim3(3 * D / 128, S / 128), 256, SMEMG>>>(
        Xc, WqkvT, nullptr, nullptr, QKV, nullptr, S, 3 * D, D);

    // 2. scores: e = exp(QK/8 - alibi) into SA + row-sum partials
    scores_tc_kernel<<<dim3(S / 128, S / 128, H), 256>>>(QKV, SA);

    // 3. deterministic row-sum reduction -> invsum
    rowsum_reduce_kernel<<<(H * S + 255) / 256, 256>>>();

    // 4. av: normalize SA in-place (write probs) and z = p @ V
    av_tc_kernel<<<dim3(S / 128, H), 256>>>(SA, QKV, Z);

    // 5. attouts = X + Z @ WO_w^T ; writes fp32 ATT + rounded ATTc
    tf32gemm_ca<3><<<dim3(D / 128, S / 128), 256, SMEMG>>>(
        Z, WOc, WOb, X, ATT, ATTc, S, D, D);

    // 6. H1 = tf32(relu(ATTc @ FF1_w^T + FF1_b))
    tf32gemm_ca<2><<<dim3(DFF / 128, S / 128), 256, SMEMG>>>(
        ATTc, FF1c, FF1b, nullptr, H1, nullptr, S, DFF, D);

    // 7. out = ATT + H1 @ FF2_w^T + FF2_b
    tf32gemm_ca<1><<<dim3(D / 128, S / 128), 256, SMEMG>>>(
        H1, FF2c, FF2b, ATT, OUT, nullptr, S, D, DFF);
}

// round 13
// speedup vs baseline: 1.3448x; 1.0998x over previous
#include <cuda_runtime.h>
#include <cstdint>

// Problem constants
#define S 2048
#define D 1024
#define H 16
#define DI 64
#define DV 64
#define DFF 4096
#define SA_ELEMS ((size_t)H * S * S)   // 67108864

// -------------------- scratch (device globals) -----------------------------
__device__ float g_WqkvT[(size_t)(3 * D) * D];   // packed transposed, tf32-rounded
__device__ float g_QKV[(size_t)S * 3 * D];       // [S, 3072] full fp32
__device__ float g_Z[(size_t)S * D];             // tf32-rounded (combine epilogue)
__device__ float g_Zp[(size_t)2 * S * D];        // split-K z partials (fp32)
__device__ float g_ATT[(size_t)S * D];           // full fp32 (residual)
__device__ float g_ATTc[(size_t)S * D];          // tf32-rounded copy
__device__ float g_H1[(size_t)S * DFF];          // tf32-rounded (FF1 epilogue)
__device__ float g_Xc[(size_t)S * D];            // tf32-rounded input
__device__ float g_WOc[(size_t)D * D];           // tf32-rounded WO_w
__device__ float g_FF1c[(size_t)DFF * D];        // tf32-rounded FF1_w
__device__ float g_FF2c[(size_t)D * DFF];        // tf32-rounded FF2_w
__device__ float g_part[(size_t)H * S * 16];     // per-(row, jt-block) exp sums

// -------------------- helpers ---------------------------------------------
__device__ __forceinline__ unsigned f2tf32(float x) {
    unsigned u;
    asm("cvt.rna.tf32.f32 %0, %1;" : "=r"(u) : "f"(x));
    return u;
}
__device__ __forceinline__ float f2tf32f(float x) { return __uint_as_float(f2tf32(x)); }

__device__ __forceinline__ float4 cvt4(float4 v) {
    float4 t;
    t.x = f2tf32f(v.x); t.y = f2tf32f(v.y);
    t.z = f2tf32f(v.z); t.w = f2tf32f(v.w);
    return t;
}

__device__ __forceinline__ void ldsm_x4(unsigned& r0, unsigned& r1, unsigned& r2, unsigned& r3,
                                        const float* p) {
    unsigned addr = (unsigned)__cvta_generic_to_shared(p);
    asm volatile("ldmatrix.sync.aligned.m8n8.x4.shared.b16 {%0,%1,%2,%3}, [%4];"
                 : "=r"(r0), "=r"(r1), "=r"(r2), "=r"(r3) : "r"(addr));
}

__device__ __forceinline__ void mma_tf32(float* c, const unsigned* a, const unsigned* b) {
    asm volatile(
        "mma.sync.aligned.m16n8k8.row.col.f32.tf32.tf32.f32 "
        "{%0,%1,%2,%3}, {%4,%5,%6,%7}, {%8,%9}, {%0,%1,%2,%3};"
        : "+f"(c[0]), "+f"(c[1]), "+f"(c[2]), "+f"(c[3])
        : "r"(a[0]), "r"(a[1]), "r"(a[2]), "r"(a[3]), "r"(b[0]), "r"(b[1]));
}

__device__ __forceinline__ void cp_async16(float* smem_dst, const float* gsrc) {
    unsigned dst = (unsigned)__cvta_generic_to_shared(smem_dst);
    asm volatile("cp.async.cg.shared.global [%0], [%1], 16;" :: "r"(dst), "l"(gsrc));
}
__device__ __forceinline__ void cp_commit() {
    asm volatile("cp.async.commit_group;");
}
template <int N>
__device__ __forceinline__ void cp_wait() {
    asm volatile("cp.async.wait_group %0;" :: "n"(N));
}

// -------------------- elementwise tf32 round (pre-convert) -----------------
__global__ void cvt_kernel(const float* __restrict__ in, float* __restrict__ out, int n4) {
    int i = blockIdx.x * 256 + threadIdx.x;
    if (i >= n4) return;
    float4 v = *(const float4*)(in + (size_t)i * 4);
    *(float4*)(out + (size_t)i * 4) = cvt4(v);
}

// -------------------- pack WQ/WK/WV transposed + round: [3072, 1024] -------
__global__ void pack_w_kernel(const float* __restrict__ WQ,
                              const float* __restrict__ WK,
                              const float* __restrict__ WV) {
    int idx = blockIdx.x * 256 + threadIdx.x;   // n*1024 + d
    if (idx >= 3 * D * D) return;
    int d = idx & 1023;
    int n = idx >> 10;
    int sect = n >> 10;
    int nn = n & 1023;
    int h = nn >> 6, e = nn & 63;
    const float* W = (sect == 0) ? WQ : (sect == 1) ? WK : WV;
    g_WqkvT[idx] = f2tf32f(W[((size_t)h * D + d) * 64 + e]);
}

// ---- tf32 GEMM, cp.async 3-stage, BK=32, single barrier per K-step --------
// C = A[MxK]*B[NxK]^T ; operands tf32-pre-rounded in gmem.
// EPI: 0 = write C
//      1 = C = acc + bias[n] + res[m,n]
//      2 = C = tf32(relu(acc + bias[n]))
//      3 = C = acc + bias[n] + res[m,n], C2 = tf32(C)
template <int EPI>
__global__ __launch_bounds__(256, 2)
void tf32gemm_ca(const float* __restrict__ A, const float* __restrict__ B,
                 const float* __restrict__ bias, const float* __restrict__ res,
                 float* __restrict__ C, float* __restrict__ C2,
                 int M, int N, int K) {
    const int BM = 128, BK = 32, LDS_ = 36, STG = 3;
    extern __shared__ float smemf[];
    float* As = smemf;                       // STG stages of BM*LDS_
    float* Bs = smemf + STG * BM * LDS_;

    int tid = threadIdx.x;
    int lane = tid & 31, warp = tid >> 5;
    int warpM = warp >> 1, warpN = warp & 1;     // 4 x 2 warp grid
    int bm = blockIdx.y * BM, bn = blockIdx.x * BM;

    float acc[2][8][4];
#pragma unroll
    for (int i = 0; i < 2; i++)
#pragma unroll
        for (int j = 0; j < 8; j++)
#pragma unroll
            for (int r = 0; r < 4; r++) acc[i][j][r] = 0.f;

    int a_row = warpM * 32 + (lane & 15);
    int a_col = (lane >> 4) * 4;
    int b_row = warpN * 64 + (lane & 7) + ((lane >> 4) << 3);
    int b_col = ((lane >> 3) & 1) * 4;

    // load mapping: 32 rows x 32 cols per pass; 4 passes cover 128 rows
    int ld_r = tid >> 3, ld_c4 = (tid & 7) * 4;
    const float* Ap = A + (size_t)(bm + ld_r) * K + ld_c4;
    const float* Bp = B + (size_t)(bn + ld_r) * K + ld_c4;
    size_t rowoff = (size_t)32 * K;

    int nk = K / BK;

    // prologue: stages 0..STG-2
#pragma unroll
    for (int s = 0; s < STG - 1; s++) {
        float* Asb = As + s * BM * LDS_;
        float* Bsb = Bs + s * BM * LDS_;
        const float* Ak = Ap + (size_t)s * BK;
        const float* Bk = Bp + (size_t)s * BK;
#pragma unroll
        for (int i = 0; i < 4; i++) {
            cp_async16(Asb + (ld_r + i * 32) * LDS_ + ld_c4, Ak + i * rowoff);
            cp_async16(Bsb + (ld_r + i * 32) * LDS_ + ld_c4, Bk + i * rowoff);
        }
        cp_commit();
    }

    for (int kt = 0; kt < nk; kt++) {
        cp_wait<STG - 2>();
        __syncthreads();   // fences arrival of stage kt and reads of stage kt-1

        if (kt + STG - 1 < nk) {
            int s = (kt + STG - 1) % STG;
            float* Asb = As + s * BM * LDS_;
            float* Bsb = Bs + s * BM * LDS_;
            const float* Ak = Ap + (size_t)(kt + STG - 1) * BK;
            const float* Bk = Bp + (size_t)(kt + STG - 1) * BK;
#pragma unroll
            for (int i = 0; i < 4; i++) {
                cp_async16(Asb + (ld_r + i * 32) * LDS_ + ld_c4, Ak + i * rowoff);
                cp_async16(Bsb + (ld_r + i * 32) * LDS_ + ld_c4, Bk + i * rowoff);
            }
            cp_commit();
        }

        const float* Asb = As + (kt % STG) * BM * LDS_;
        const float* Bsb = Bs + (kt % STG) * BM * LDS_;
#pragma unroll
        for (int ks = 0; ks < 4; ks++) {
            unsigned af[2][4];
            unsigned bf[8][2];
#pragma unroll
            for (int mt = 0; mt < 2; mt++) {
                ldsm_x4(af[mt][0], af[mt][1], af[mt][2], af[mt][3],
                        &Asb[(a_row + mt * 16) * LDS_ + ks * 8 + a_col]);
            }
#pragma unroll
            for (int np = 0; np < 4; np++) {
                ldsm_x4(bf[2 * np][0], bf[2 * np][1], bf[2 * np + 1][0], bf[2 * np + 1][1],
                        &Bsb[(b_row + np * 16) * LDS_ + ks * 8 + b_col]);
            }
#pragma unroll
            for (int mt = 0; mt < 2; mt++)
#pragma unroll
                for (int nt = 0; nt < 8; nt++)
                    mma_tf32(acc[mt][nt], af[mt], bf[nt]);
        }
    }

    int g = lane >> 2, c2 = (lane & 3) * 2;
#pragma unroll
    for (int mt = 0; mt < 2; mt++) {
#pragma unroll
        for (int half = 0; half < 2; half++) {
            int m = bm + warpM * 32 + mt * 16 + g + half * 8;
#pragma unroll
            for (int nt = 0; nt < 8; nt++) {
                int n = bn + warpN * 64 + nt * 8 + c2;
                float v0 = acc[mt][nt][half * 2 + 0];
                float v1 = acc[mt][nt][half * 2 + 1];
                if (EPI >= 1) { v0 += bias[n]; v1 += bias[n + 1]; }
                if (EPI == 1 || EPI == 3) {
                    float2 rr = *(const float2*)(res + (size_t)m * N + n);
                    v0 += rr.x; v1 += rr.y;
                }
                if (EPI == 2) {
                    v0 = f2tf32f(fmaxf(v0, 0.f));
                    v1 = f2tf32f(fmaxf(v1, 0.f));
                }
                float2 o; o.x = v0; o.y = v1;
                *(float2*)(C + (size_t)m * N + n) = o;
                if (EPI == 3) {
                    float2 oc; oc.x = f2tf32f(v0); oc.y = f2tf32f(v1);
                    *(float2*)(C2 + (size_t)m * N + n) = oc;
                }
            }
        }
    }
}

// ---- scores: write e = exp(QK/8 - alibi) (0 above diag) + row-sum partials -
__global__ __launch_bounds__(256, 2)
void scores_tc_kernel(const float* __restrict__ QKV, float* __restrict__ SA) {
    const int LDS_ = 20;
    int jt = blockIdx.x, it = blockIdx.y, h = blockIdx.z;
    int bm = it * 128, bn = jt * 128;
    float* out = SA + ((size_t)h * S + bm) * S + bn;
    int tid = threadIdx.x;

    if (jt > it) {   // strictly above diagonal at 128-granularity: zeros
#pragma unroll
        for (int r = 0; r < 16; r++) {
            int id = tid + r * 256;
            int row = id >> 5, c4 = (id & 31) * 4;
            *(float4*)(out + (size_t)row * S + c4) = make_float4(0.f, 0.f, 0.f, 0.f);
        }
        return;
    }

    __shared__ float Qh[128 * LDS_], Ql[128 * LDS_];
    __shared__ float Kh[128 * LDS_], Kl[128 * LDS_];
    __shared__ float blksum[128];

    int lane = tid & 31, warp = tid >> 5;
    int warpM = warp >> 1, warpN = warp & 1;

    if (tid < 128) blksum[tid] = 0.f;

    float acc[2][8][4];
#pragma unroll
    for (int i = 0; i < 2; i++)
#pragma unroll
        for (int j = 0; j < 8; j++)
#pragma unroll
            for (int r = 0; r < 4; r++) acc[i][j][r] = 0.f;

    int a_row = warpM * 32 + (lane & 15);
    int a_col = (lane >> 4) * 4;
    int b_row = warpN * 64 + (lane & 7) + ((lane >> 4) << 3);
    int b_col = ((lane >> 3) & 1) * 4;

    const float* Qb = QKV + (size_t)bm * (3 * D) + h * 64;
    const float* Kb = QKV + (size_t)bn * (3 * D) + D + h * 64;

    for (int kc = 0; kc < 4; kc++) {
#pragma unroll
        for (int i = 0; i < 2; i++) {
            int id = tid + i * 256;
            int row = id >> 2, c4 = (id & 3) * 4;
            float4 q = *(const float4*)(Qb + (size_t)row * (3 * D) + kc * 16 + c4);
            float4 k = *(const float4*)(Kb + (size_t)row * (3 * D) + kc * 16 + c4);
            float4 qh = cvt4(q), kh = cvt4(k);
            float4 ql, kl;
            ql.x = f2tf32f(q.x - qh.x); ql.y = f2tf32f(q.y - qh.y);
            ql.z = f2tf32f(q.z - qh.z); ql.w = f2tf32f(q.w - qh.w);
            kl.x = f2tf32f(k.x - kh.x); kl.y = f2tf32f(k.y - kh.y);
            kl.z = f2tf32f(k.z - kh.z); kl.w = f2tf32f(k.w - kh.w);
            *(float4*)&Qh[row * LDS_ + c4] = qh;
            *(float4*)&Ql[row * LDS_ + c4] = ql;
            *(float4*)&Kh[row * LDS_ + c4] = kh;
            *(float4*)&Kl[row * LDS_ + c4] = kl;
        }
        __syncthreads();

#pragma unroll
        for (int ks = 0; ks < 2; ks++) {
            unsigned afh[2][4], afl[2][4];
            unsigned bfh[8][2], bfl[8][2];
#pragma unroll
            for (int mt = 0; mt < 2; mt++) {
                ldsm_x4(afh[mt][0], afh[mt][1], afh[mt][2], afh[mt][3],
                        &Qh[(a_row + mt * 16) * LDS_ + ks * 8 + a_col]);
                ldsm_x4(afl[mt][0], afl[mt][1], afl[mt][2], afl[mt][3],
                        &Ql[(a_row + mt * 16) * LDS_ + ks * 8 + a_col]);
            }
#pragma unroll
            for (int np = 0; np < 4; np++) {
                ldsm_x4(bfh[2 * np][0], bfh[2 * np][1], bfh[2 * np + 1][0], bfh[2 * np + 1][1],
                        &Kh[(b_row + np * 16) * LDS_ + ks * 8 + b_col]);
                ldsm_x4(bfl[2 * np][0], bfl[2 * np][1], bfl[2 * np + 1][0], bfl[2 * np + 1][1],
                        &Kl[(b_row + np * 16) * LDS_ + ks * 8 + b_col]);
            }
#pragma unroll
            for (int mt = 0; mt < 2; mt++)
#pragma unroll
                for (int nt = 0; nt < 8; nt++) {
                    mma_tf32(acc[mt][nt], afh[mt], bfh[nt]);
                    mma_tf32(acc[mt][nt], afh[mt], bfl[nt]);
                    mma_tf32(acc[mt][nt], afl[mt], bfh[nt]);
                }
        }
        __syncthreads();
    }

    float slope = exp2f(-0.5f * (float)(h + 1));
    int g = lane >> 2, c2 = (lane & 3) * 2;
#pragma unroll
    for (int mt = 0; mt < 2; mt++) {
#pragma unroll
        for (int half = 0; half < 2; half++) {
            int li = warpM * 32 + mt * 16 + g + half * 8;
            int gi = bm + li;
            float rs = 0.f;
#pragma unroll
            for (int nt = 0; nt < 8; nt++) {
                int lj = warpN * 64 + nt * 8 + c2;
                int gj = bn + lj;
                float v0 = acc[mt][nt][half * 2 + 0];
                float v1 = acc[mt][nt][half * 2 + 1];
                float e0 = (gj <= gi)
                    ? __expf(v0 * 0.125f - (float)(gi - gj) * slope) : 0.f;
                float e1 = (gj + 1 <= gi)
                    ? __expf(v1 * 0.125f - (float)(gi - gj - 1) * slope) : 0.f;
                rs += e0 + e1;
                float2 o; o.x = e0; o.y = e1;
                *(float2*)(out + (size_t)li * S + lj) = o;
            }
            rs += __shfl_xor_sync(0xffffffffu, rs, 1);
            rs += __shfl_xor_sync(0xffffffffu, rs, 2);
            if ((lane & 3) == 0) atomicAdd(&blksum[li], rs);
        }
    }
    __syncthreads();
    if (tid < 128)
        g_part[((size_t)h * S + bm + tid) * 16 + jt] = blksum[tid];
}

// ---- av split-K: p = e*invsum written back; z-partial = p @ V -------------
// grid (S/128, H, 2); split handles half of this band's j-chunks.
__global__ __launch_bounds__(256, 2)
void av_tc_kernel(float* __restrict__ SA, const float* __restrict__ QKV,
                  float* __restrict__ Zp) {
    const int LDS_ = 20;
    int bi = (S / 128 - 1) - blockIdx.x;     // heavy bands launch first
    int h = blockIdx.y;
    int split = blockIdx.z;
    int bm = bi * 128;
    int tid = threadIdx.x;
    int lane = tid & 31, warp = tid >> 5;

    __shared__ float SAs[2][128 * LDS_];
    __shared__ float Vs[2][64 * LDS_];
    __shared__ float sinv[128];

    // per-block invsum for this band's 128 rows (partials from scores)
    if (tid < 128) {
        const float* p = g_part + ((size_t)h * S + bm + tid) * 16;
        float s = 0.f;
        for (int j = 0; j <= bi; j++) s += p[j];
        sinv[tid] = 1.f / s;
    }
    __syncthreads();

    float acc[8][4];
#pragma unroll
    for (int j = 0; j < 8; j++)
#pragma unroll
        for (int r = 0; r < 4; r++) acc[j][r] = 0.f;

    int a_row = warp * 16 + (lane & 15);
    int a_col = (lane >> 4) * 4;
    int b_row = (lane & 7) + ((lane >> 4) << 3);
    int b_col = ((lane >> 3) & 1) * 4;

    float* SAb = SA + ((size_t)h * S + bm) * S;
    const float* Vb = QKV + 2 * D + (size_t)h * 64;

    int ldrow = tid >> 2, ld_c4 = (tid & 3) * 4;
    float inv0 = sinv[ldrow];
    float inv1 = sinv[ldrow + 64];
    int jloc = tid >> 6, vcol = tid & 63;

    int nchunks = (bm + 128) / 16;
    int c0 = split ? nchunks / 2 : 0;
    int c1 = split ? nchunks : nchunks / 2;

    float4 ra0, ra1;
    float rv[4];

    // prologue: load + store chunk c0
    {
        int k0 = c0 * 16;
        ra0 = *(const float4*)(SAb + (size_t)ldrow * S + k0 + ld_c4);
        ra1 = *(const float4*)(SAb + (size_t)(ldrow + 64) * S + k0 + ld_c4);
#pragma unroll
        for (int i = 0; i < 4; i++)
            rv[i] = Vb[(size_t)(k0 + jloc + i * 4) * (3 * D) + vcol];

        ra0.x *= inv0; ra0.y *= inv0; ra0.z *= inv0; ra0.w *= inv0;
        ra1.x *= inv1; ra1.y *= inv1; ra1.z *= inv1; ra1.w *= inv1;
        *(float4*)(SAb + (size_t)ldrow * S + k0 + ld_c4) = ra0;
        *(float4*)(SAb + (size_t)(ldrow + 64) * S + k0 + ld_c4) = ra1;
        *(float4*)&SAs[0][ldrow * LDS_ + ld_c4] = cvt4(ra0);
        *(float4*)&SAs[0][(ldrow + 64) * LDS_ + ld_c4] = cvt4(ra1);
#pragma unroll
        for (int i = 0; i < 4; i++)
            Vs[0][vcol * LDS_ + jloc + i * 4] = f2tf32f(rv[i]);
    }
    __syncthreads();

    for (int kc = c0; kc < c1; kc++) {
        int buf = (kc - c0) & 1;
        bool more = (kc + 1) < c1;

        if (more) {   // prefetch chunk kc+1 into registers
            int k0 = (kc + 1) * 16;
            ra0 = *(const float4*)(SAb + (size_t)ldrow * S + k0 + ld_c4);
            ra1 = *(const float4*)(SAb + (size_t)(ldrow + 64) * S + k0 + ld_c4);
#pragma unroll
            for (int i = 0; i < 4; i++)
                rv[i] = Vb[(size_t)(k0 + jloc + i * 4) * (3 * D) + vcol];
        }

#pragma unroll
        for (int ks = 0; ks < 2; ks++) {
            unsigned af[4];
            unsigned bf[8][2];
            ldsm_x4(af[0], af[1], af[2], af[3],
                    &SAs[buf][a_row * LDS_ + ks * 8 + a_col]);
#pragma unroll
            for (int np = 0; np < 4; np++) {
                ldsm_x4(bf[2 * np][0], bf[2 * np][1], bf[2 * np + 1][0], bf[2 * np + 1][1],
                        &Vs[buf][(b_row + np * 16) * LDS_ + ks * 8 + b_col]);
            }
#pragma unroll
            for (int nt = 0; nt < 8; nt++)
                mma_tf32(acc[nt], af, bf[nt]);
        }

        if (more) {   // scale, write back to gmem, store smem for next iter
            int k0 = (kc + 1) * 16;
            int nb = buf ^ 1;
            ra0.x *= inv0; ra0.y *= inv0; ra0.z *= inv0; ra0.w *= inv0;
            ra1.x *= inv1; ra1.y *= inv1; ra1.z *= inv1; ra1.w *= inv1;
            *(float4*)(SAb + (size_t)ldrow * S + k0 + ld_c4) = ra0;
            *(float4*)(SAb + (size_t)(ldrow + 64) * S + k0 + ld_c4) = ra1;
            *(float4*)&SAs[nb][ldrow * LDS_ + ld_c4] = cvt4(ra0);
            *(float4*)&SAs[nb][(ldrow + 64) * LDS_ + ld_c4] = cvt4(ra1);
#pragma unroll
            for (int i = 0; i < 4; i++)
                Vs[nb][vcol * LDS_ + jloc + i * 4] = f2tf32f(rv[i]);
            __syncthreads();
        }
    }

    // write raw fp32 partial for this split
    float* Zout = Zp + (size_t)split * S * D;
    int g = lane >> 2, c2 = (lane & 3) * 2;
#pragma unroll
    for (int half = 0; half < 2; half++) {
        int m = bm + warp * 16 + g + half * 8;
#pragma unroll
        for (int nt = 0; nt < 8; nt++) {
            int n = h * 64 + nt * 8 + c2;
            float2 o;
            o.x = acc[nt][half * 2 + 0];
            o.y = acc[nt][half * 2 + 1];
            *(float2*)(Zout + (size_t)m * D + n) = o;
        }
    }
}

// ---- combine z partials: Z = tf32(p0 + p1) --------------------------------
__global__ void z_combine_kernel(const float* __restrict__ Zp, float* __restrict__ Z,
                                 int n4) {
    int i = blockIdx.x * 256 + threadIdx.x;
    if (i >= n4) return;
    float4 a = *(const float4*)(Zp + (size_t)i * 4);
    float4 b = *(const float4*)(Zp + (size_t)(i + n4) * 4);
    float4 s;
    s.x = a.x + b.x; s.y = a.y + b.y; s.z = a.z + b.z; s.w = a.w + b.w;
    *(float4*)(Z + (size_t)i * 4) = cvt4(s);
}

// --------------------------- launch ---------------------------------------
extern "C" void kernel_launch(void* const* d_in, const int* in_sizes, int n_in,
                              void* d_out, int out_size) {
    const float* X    = (const float*)d_in[0];
    const float* WQ   = (const float*)d_in[1];
    const float* WK   = (const float*)d_in[2];
    const float* WV   = (const float*)d_in[3];
    const float* WOw  = (const float*)d_in[4];
    const float* WOb  = (const float*)d_in[5];
    const float* FF1w = (const float*)d_in[6];
    const float* FF1b = (const float*)d_in[7];
    const float* FF2w = (const float*)d_in[8];
    const float* FF2b = (const float*)d_in[9];

    float* SA  = (float*)d_out;
    float* OUT = (float*)d_out + SA_ELEMS;

    float *WqkvT, *QKV, *Z, *Zp, *ATT, *ATTc, *H1, *Xc, *WOc, *FF1c, *FF2c;
    cudaGetSymbolAddress((void**)&WqkvT, g_WqkvT);
    cudaGetSymbolAddress((void**)&QKV, g_QKV);
    cudaGetSymbolAddress((void**)&Z, g_Z);
    cudaGetSymbolAddress((void**)&Zp, g_Zp);
    cudaGetSymbolAddress((void**)&ATT, g_ATT);
    cudaGetSymbolAddress((void**)&ATTc, g_ATTc);
    cudaGetSymbolAddress((void**)&H1, g_H1);
    cudaGetSymbolAddress((void**)&Xc, g_Xc);
    cudaGetSymbolAddress((void**)&WOc, g_WOc);
    cudaGetSymbolAddress((void**)&FF1c, g_FF1c);
    cudaGetSymbolAddress((void**)&FF2c, g_FF2c);

    // dynamic smem: 3 stages x 256 rows x 36 floats = 110592 B
    const int SMEMG = 3 * 256 * 36 * 4;
    cudaFuncSetAttribute(tf32gemm_ca<0>, cudaFuncAttributeMaxDynamicSharedMemorySize, SMEMG);
    cudaFuncSetAttribute(tf32gemm_ca<1>, cudaFuncAttributeMaxDynamicSharedMemorySize, SMEMG);
    cudaFuncSetAttribute(tf32gemm_ca<2>, cudaFuncAttributeMaxDynamicSharedMemorySize, SMEMG);
    cudaFuncSetAttribute(tf32gemm_ca<3>, cudaFuncAttributeMaxDynamicSharedMemorySize, SMEMG);

    // 0. pre-round all GEMM operands to tf32 (rna) once
    pack_w_kernel<<<(3 * D * D + 255) / 256, 256>>>(WQ, WK, WV);
    cvt_kernel<<<(S * D / 4 + 255) / 256, 256>>>(X, Xc, S * D / 4);
    cvt_kernel<<<(D * D / 4 + 255) / 256, 256>>>(WOw, WOc, D * D / 4);
    cvt_kernel<<<(DFF * D / 4 + 255) / 256, 256>>>(FF1w, FF1c, DFF * D / 4);
    cvt_kernel<<<(D * DFF / 4 + 255) / 256, 256>>>(FF2w, FF2c, D * DFF / 4);

    // 1. QKV projection
    tf32gemm_ca<0><<<dim3(3 * D / 128, S / 128), 256, SMEMG>>>(
        Xc, WqkvT, nullptr, nullptr, QKV, nullptr, S, 3 * D, D);

    // 2. scores: e = exp(QK/8 - alibi) into SA + row-sum partials
    scores_tc_kernel<<<dim3(S / 128, S / 128, H), 256>>>(QKV, SA);

    // 3. av split-K: normalize SA in-place, z partials
    av_tc_kernel<<<dim3(S / 128, H, 2), 256>>>(SA, QKV, Zp);

    // 4. combine partials -> Z (tf32-rounded)
    z_combine_kernel<<<(S * D / 4 + 255) / 256, 256>>>(Zp, Z, S * D / 4);

    // 5. attouts = X + Z @ WO_w^T ; writes fp32 ATT + rounded ATTc
    tf32gemm_ca<3><<<dim3(D / 128, S / 128), 256, SMEMG>>>(
        Z, WOc, WOb, X, ATT, ATTc, S, D, D);

    // 6. H1 = tf32(relu(ATTc @ FF1_w^T + FF1_b))
    tf32gemm_ca<2><<<dim3(DFF / 128, S / 128), 256, SMEMG>>>(
        ATTc, FF1c, FF1b, nullptr, H1, nullptr, S, DFF, D);

    // 7. out = ATT + H1 @ FF2_w^T + FF2_b
    tf32gemm_ca<1><<<dim3(D / 128, S / 128), 256, SMEMG>>>(
        H1, FF2c, FF2b, ATT, OUT, nullptr, S, D, DFF);
}